// round 9
// baseline (speedup 1.0000x reference)
#include <cuda_runtime.h>
#include <cstdint>

// ---------------- static device scratch (no allocations allowed) ----------------
__device__ float g_T3[4096 * 512];      // 8 MB : in-contracted activations (tf32 bits)
__device__ float g_U [4096 * 512];      // 8 MB : core-contracted activations (fp32)
__device__ float g_coreTF[512 * 512];   // 1 MB : core pre-converted to tf32 bits

__device__ __forceinline__ uint32_t f2tf32(float f) {
    uint32_t u;
    asm("cvt.rna.tf32.f32 %0, %1;" : "=r"(u) : "f"(f));
    return u;
}
__device__ __forceinline__ uint32_t smem_u32(const void* p) {
    uint32_t a;
    asm("{ .reg .u64 t; cvta.to.shared.u64 t, %1; cvt.u32.u64 %0, t; }" : "=r"(a) : "l"(p));
    return a;
}
#define CP_ASYNC16(dst, src) \
    asm volatile("cp.async.cg.shared.global [%0], [%1], 16;" :: "r"(dst), "l"(src) : "memory")
#define CP_COMMIT() asm volatile("cp.async.commit_group;" ::: "memory")
#define CP_WAIT(n)  asm volatile("cp.async.wait_group %0;" :: "n"(n) : "memory")

// ---------------- K0: pre-convert core to tf32 bits ----------------
__global__ __launch_bounds__(256) void k_cvtcore(const float* __restrict__ core) {
    int i = (blockIdx.x * 256 + threadIdx.x) * 4;
    float4 v = *(const float4*)(core + i);
    uint4 o = make_uint4(f2tf32(v.x), f2tf32(v.y), f2tf32(v.z), f2tf32(v.w));
    *(uint4*)(g_coreTF + i) = o;
}

// ---------------- K1: stage A, warp-per-sample, vectorized x loads ----------------
static constexpr int T1L = 272;
static constexpr int T2L = 144;
static constexpr int WSM = 8 * T1L + 8 * T2L;               // 3328 floats / warp
static constexpr int SMEM_A = (8 * WSM + 384) * 4;          // 108032 B

__global__ __launch_bounds__(256, 2) void k_stageA(const float* __restrict__ x,
                                                   const float* __restrict__ f3,
                                                   const float* __restrict__ f4,
                                                   const float* __restrict__ f5) {
    extern __shared__ float sm[];
    float* f3s = sm + 8 * WSM;
    float* f4s = f3s + 128;
    float* f5s = f4s + 128;

    int t = threadIdx.x, wid = t >> 5, lane = t & 31;
    if (t < 128) { f3s[t] = f3[t]; f4s[t] = f4[t]; f5s[t] = f5[t]; }
    __syncthreads();

    float* t1w = sm + wid * WSM;
    float* t2w = t1w + 8 * T1L;

    long s = (long)blockIdx.x * 8 + wid;
    const float* xs = x + s * 4096;

    // ---- phase 1: float4 loads (ef = 4*lane + q + 128*j) ----
    {
        float acc[2][4][8];   // [j][q][l]
#pragma unroll
        for (int j = 0; j < 2; j++)
#pragma unroll
            for (int q = 0; q < 4; q++)
#pragma unroll
                for (int l = 0; l < 8; l++) acc[j][q][l] = 0.f;
#pragma unroll 4
        for (int d = 0; d < 16; d++) {
            float4 xv0 = *(const float4*)(xs + d * 256 + 4 * lane);
            float4 xv1 = *(const float4*)(xs + d * 256 + 4 * lane + 128);
            float xv[2][4] = { {xv0.x, xv0.y, xv0.z, xv0.w},
                               {xv1.x, xv1.y, xv1.z, xv1.w} };
#pragma unroll
            for (int l = 0; l < 8; l++) {
                float fv = f3s[d * 8 + l];
#pragma unroll
                for (int j = 0; j < 2; j++)
#pragma unroll
                    for (int q = 0; q < 4; q++)
                        acc[j][q][l] += xv[j][q] * fv;
            }
        }
#pragma unroll
        for (int l = 0; l < 8; l++)
#pragma unroll
            for (int j = 0; j < 2; j++) {
                float4 v = make_float4(acc[j][0][l], acc[j][1][l],
                                       acc[j][2][l], acc[j][3][l]);
                *(float4*)(t1w + l * T1L + 4 * lane + 128 * j) = v;
            }
    }
    __syncwarp();

    // ---- phase 2 ----
    {
        float acc[4][8];
#pragma unroll
        for (int q = 0; q < 4; q++)
#pragma unroll
            for (int m = 0; m < 8; m++) acc[q][m] = 0.f;
#pragma unroll
        for (int e = 0; e < 16; e++) {
            float tv[4];
#pragma unroll
            for (int q = 0; q < 4; q++) {
                int p = lane + 32 * q, l = p >> 4, f = p & 15;
                tv[q] = t1w[l * T1L + e * 16 + f];
            }
#pragma unroll
            for (int m = 0; m < 8; m++) {
                float fv = f4s[e * 8 + m];
#pragma unroll
                for (int q = 0; q < 4; q++) acc[q][m] += tv[q] * fv;
            }
        }
#pragma unroll
        for (int q = 0; q < 4; q++) {
            int p = lane + 32 * q, l = p >> 4, f = p & 15;
#pragma unroll
            for (int m = 0; m < 8; m++)
                t2w[l * T2L + m * 17 + f] = acc[q][m];
        }
    }
    __syncwarp();

    // ---- phase 3 -> g_T3 (tf32 bits) ----
    {
#pragma unroll
        for (int h = 0; h < 2; h++) {
            int lm = lane + 32 * h, l = lm >> 3, m = lm & 7;
            float acc[8];
#pragma unroll
            for (int n = 0; n < 8; n++) acc[n] = 0.f;
#pragma unroll
            for (int f = 0; f < 16; f++) {
                float tv = t2w[l * T2L + m * 17 + f];
#pragma unroll
                for (int n = 0; n < 8; n++) acc[n] += tv * f5s[f * 8 + n];
            }
            uint4* dst = (uint4*)(g_T3 + s * 512 + lm * 8);
            dst[0] = make_uint4(f2tf32(acc[0]), f2tf32(acc[1]), f2tf32(acc[2]), f2tf32(acc[3]));
            dst[1] = make_uint4(f2tf32(acc[4]), f2tf32(acc[5]), f2tf32(acc[6]), f2tf32(acc[7]));
        }
    }
}

// ---------------- K2: stage B via mma.sync tf32, 128x64 tiles, 2 CTAs/SM ----------------
// 256 threads, 8 warps (4m x 2n), each warp 32x32. K chunks of 32, 3-deep pipeline.
static constexpr int GS = 36;
static constexpr int A_ST = 128 * GS;                  // words per A stage
static constexpr int B_ST = 64 * GS;                   // words per B stage
static constexpr int GEMM_SMEM = 3 * (A_ST + B_ST) * 4;  // 82944 B

__global__ __launch_bounds__(256, 2) void k_gemm_mma() {
    extern __shared__ float sm[];
    uint32_t sm_u = smem_u32(sm);

    int t = threadIdx.x;
    int lane = t & 31, wid = t >> 5;
    int warp_m = (wid & 3) * 32;
    int warp_n = (wid >> 2) * 32;
    long s0 = (long)blockIdx.x * 128;
    int n0 = blockIdx.y * 64;

    // A: 4 float4 per thread per chunk; B: 2 float4 per thread per chunk
    int ra[4], ca[4], rb[2], cb[2];
#pragma unroll
    for (int i = 0; i < 4; i++) { int ii = t + 256 * i; ra[i] = ii >> 3; ca[i] = (ii & 7) * 4; }
#pragma unroll
    for (int i = 0; i < 2; i++) { int ii = t + 256 * i; rb[i] = ii >> 3; cb[i] = (ii & 7) * 4; }

    const float* AGp[4]; uint32_t Ad[4];
#pragma unroll
    for (int i = 0; i < 4; i++) {
        AGp[i] = g_T3 + (s0 + ra[i]) * 512 + ca[i];
        Ad[i] = (uint32_t)((ra[i] * GS + ca[i]) * 4);
    }
    const float* BGp[2]; uint32_t Bd[2];
#pragma unroll
    for (int i = 0; i < 2; i++) {
        BGp[i] = g_coreTF + (size_t)(n0 + rb[i]) * 512 + cb[i];
        Bd[i] = (uint32_t)((rb[i] * GS + cb[i]) * 4);
    }

    float acc[2][4][4];
#pragma unroll
    for (int mt = 0; mt < 2; mt++)
#pragma unroll
        for (int nt = 0; nt < 4; nt++)
#pragma unroll
            for (int i = 0; i < 4; i++) acc[mt][nt][i] = 0.f;

    int fr = lane >> 2, fc = lane & 3;

    // prologue: issue chunks 0,1
#pragma unroll
    for (int pc = 0; pc < 2; pc++) {
        uint32_t Au = sm_u + pc * A_ST * 4;
        uint32_t Bu = sm_u + (3 * A_ST + pc * B_ST) * 4;
#pragma unroll
        for (int i = 0; i < 4; i++) CP_ASYNC16(Au + Ad[i], AGp[i] + pc * 32);
#pragma unroll
        for (int i = 0; i < 2; i++) CP_ASYNC16(Bu + Bd[i], BGp[i] + pc * 32);
        CP_COMMIT();
    }

#pragma unroll 1
    for (int c = 0; c < 16; c++) {
        int p = c % 3;
        if (c == 15) { CP_WAIT(0); } else { CP_WAIT(1); }
        __syncthreads();

        const float* As = sm + p * A_ST;
        const float* Bs = sm + 3 * A_ST + p * B_ST;
#pragma unroll
        for (int ks = 0; ks < 4; ks++) {
            int k0 = ks * 8;
            uint32_t a[2][4], b[4][2];
#pragma unroll
            for (int mt = 0; mt < 2; mt++) {
                const float* ab = As + (warp_m + mt * 16 + fr) * GS + k0 + fc;
                a[mt][0] = __float_as_uint(ab[0]);
                a[mt][1] = __float_as_uint(ab[8 * GS]);
                a[mt][2] = __float_as_uint(ab[4]);
                a[mt][3] = __float_as_uint(ab[8 * GS + 4]);
            }
#pragma unroll
            for (int nt = 0; nt < 4; nt++) {
                const float* bb = Bs + (warp_n + nt * 8 + fr) * GS + k0 + fc;
                b[nt][0] = __float_as_uint(bb[0]);
                b[nt][1] = __float_as_uint(bb[4]);
            }
#pragma unroll
            for (int mt = 0; mt < 2; mt++)
#pragma unroll
                for (int nt = 0; nt < 4; nt++)
                    asm volatile(
                        "mma.sync.aligned.m16n8k8.row.col.f32.tf32.tf32.f32 "
                        "{%0,%1,%2,%3}, {%4,%5,%6,%7}, {%8,%9}, {%0,%1,%2,%3};"
                        : "+f"(acc[mt][nt][0]), "+f"(acc[mt][nt][1]),
                          "+f"(acc[mt][nt][2]), "+f"(acc[mt][nt][3])
                        : "r"(a[mt][0]), "r"(a[mt][1]), "r"(a[mt][2]), "r"(a[mt][3]),
                          "r"(b[nt][0]), "r"(b[nt][1]));
        }

        if (c + 2 < 16) {
            int pn = (c + 2) % 3;
            uint32_t Au = sm_u + pn * A_ST * 4;
            uint32_t Bu = sm_u + (3 * A_ST + pn * B_ST) * 4;
            int off = (c + 2) * 32;
#pragma unroll
            for (int i = 0; i < 4; i++) CP_ASYNC16(Au + Ad[i], AGp[i] + off);
#pragma unroll
            for (int i = 0; i < 2; i++) CP_ASYNC16(Bu + Bd[i], BGp[i] + off);
            CP_COMMIT();
        }
    }

    // epilogue
    int cp = (lane & 3) * 2;
#pragma unroll
    for (int mt = 0; mt < 2; mt++)
#pragma unroll
        for (int h = 0; h < 2; h++) {
            long m = s0 + warp_m + mt * 16 + fr + h * 8;
            float* dst = g_U + m * 512 + n0 + warp_n + cp;
#pragma unroll
            for (int nt = 0; nt < 4; nt++) {
                float2 v = make_float2(acc[mt][nt][h * 2], acc[mt][nt][h * 2 + 1]);
                *(float2*)(dst + nt * 8) = v;
            }
        }
}

// ---------------- K3: stage C (block version, 4 samples/block) ----------------
__global__ __launch_bounds__(256) void k_stageC(const float* __restrict__ f0,
                                                const float* __restrict__ f1,
                                                const float* __restrict__ f2,
                                                const float* __restrict__ bias,
                                                float* __restrict__ y) {
    extern __shared__ float sm[];
    float* u1s = sm;                    // 4 * 1152
    float* u2s = sm + 4 * 1152;         // 4 * 2176
    float* f0s = u2s + 4 * 2176;
    float* f1s = f0s + 128;
    float* f2s = f1s + 128;

    int t = threadIdx.x;
    if (t < 128) { f0s[t] = f0[t]; f1s[t] = f1[t]; f2s[t] = f2[t]; }
    __syncthreads();

    long s0 = (long)blockIdx.x * 4;

    {
        int g = t >> 6, jk = t & 63;
        float acc[4][4];
#pragma unroll
        for (int s = 0; s < 4; s++)
#pragma unroll
            for (int a4 = 0; a4 < 4; a4++) acc[s][a4] = 0.f;
#pragma unroll
        for (int i = 0; i < 8; i++) {
            float uv0 = g_U[(s0 + 0) * 512 + i * 64 + jk];
            float uv1 = g_U[(s0 + 1) * 512 + i * 64 + jk];
            float uv2 = g_U[(s0 + 2) * 512 + i * 64 + jk];
            float uv3 = g_U[(s0 + 3) * 512 + i * 64 + jk];
#pragma unroll
            for (int a4 = 0; a4 < 4; a4++) {
                float fv = f0s[(g * 4 + a4) * 8 + i];
                acc[0][a4] += uv0 * fv; acc[1][a4] += uv1 * fv;
                acc[2][a4] += uv2 * fv; acc[3][a4] += uv3 * fv;
            }
        }
#pragma unroll
        for (int s = 0; s < 4; s++)
#pragma unroll
            for (int a4 = 0; a4 < 4; a4++)
                u1s[s * 1152 + (g * 4 + a4) * 72 + jk] = acc[s][a4];
    }
    __syncthreads();

    {
        int h = t >> 7, pair = t & 127;
        int a = pair >> 3, k = pair & 7;
        float acc[2][16];
#pragma unroll
        for (int z = 0; z < 2; z++)
#pragma unroll
            for (int b = 0; b < 16; b++) acc[z][b] = 0.f;
#pragma unroll
        for (int j = 0; j < 8; j++) {
            float tv0 = u1s[(2 * h + 0) * 1152 + a * 72 + j * 8 + k];
            float tv1 = u1s[(2 * h + 1) * 1152 + a * 72 + j * 8 + k];
#pragma unroll
            for (int b = 0; b < 16; b++) {
                float fv = f1s[b * 8 + j];
                acc[0][b] += tv0 * fv; acc[1][b] += tv1 * fv;
            }
        }
#pragma unroll
        for (int z = 0; z < 2; z++)
#pragma unroll
            for (int b = 0; b < 16; b++)
                u2s[(2 * h + z) * 2176 + a * 136 + b * 8 + k] = acc[z][b];
    }
    __syncthreads();

    {
        int q = t & 3, ab0 = t >> 2;
#pragma unroll
        for (int r = 0; r < 4; r++) {
            int ab = ab0 + 64 * r;
            int a = ab >> 4, b = ab & 15;
            float acc[4][4];
#pragma unroll
            for (int s = 0; s < 4; s++)
#pragma unroll
                for (int c4 = 0; c4 < 4; c4++) acc[s][c4] = 0.f;
#pragma unroll
            for (int k = 0; k < 8; k++) {
                float tv0 = u2s[0 * 2176 + a * 136 + b * 8 + k];
                float tv1 = u2s[1 * 2176 + a * 136 + b * 8 + k];
                float tv2 = u2s[2 * 2176 + a * 136 + b * 8 + k];
                float tv3 = u2s[3 * 2176 + a * 136 + b * 8 + k];
#pragma unroll
                for (int c4 = 0; c4 < 4; c4++) {
                    float fv = f2s[(q * 4 + c4) * 8 + k];
                    acc[0][c4] += tv0 * fv; acc[1][c4] += tv1 * fv;
                    acc[2][c4] += tv2 * fv; acc[3][c4] += tv3 * fv;
                }
            }
            float4 bv = *(const float4*)&bias[ab * 16 + q * 4];
#pragma unroll
            for (int s = 0; s < 4; s++) {
                float4 o = make_float4(acc[s][0] + bv.x, acc[s][1] + bv.y,
                                       acc[s][2] + bv.z, acc[s][3] + bv.w);
                *(float4*)&y[(s0 + s) * 4096 + ab * 16 + q * 4] = o;
            }
        }
    }
}

// ---------------- launch ----------------
extern "C" void kernel_launch(void* const* d_in, const int* in_sizes, int n_in,
                              void* d_out, int out_size) {
    const float* x    = (const float*)d_in[0];
    const float* core = (const float*)d_in[1];
    const float* f0   = (const float*)d_in[2];
    const float* f1   = (const float*)d_in[3];
    const float* f2   = (const float*)d_in[4];
    const float* f3   = (const float*)d_in[5];
    const float* f4   = (const float*)d_in[6];
    const float* f5   = (const float*)d_in[7];
    const float* bias = (const float*)d_in[8];
    float* y = (float*)d_out;

    int N = in_sizes[0] / 4096;

    const int SMEM_C = (4 * 1152 + 4 * 2176 + 384) * 4;   // 54784

    cudaFuncSetAttribute(k_stageA, cudaFuncAttributeMaxDynamicSharedMemorySize, SMEM_A);
    cudaFuncSetAttribute(k_gemm_mma, cudaFuncAttributeMaxDynamicSharedMemorySize, GEMM_SMEM);
    cudaFuncSetAttribute(k_stageC, cudaFuncAttributeMaxDynamicSharedMemorySize, SMEM_C);

    k_cvtcore<<<256, 256>>>(core);
    k_stageA<<<N / 8, 256, SMEM_A>>>(x, f3, f4, f5);
    k_gemm_mma<<<dim3(N / 128, 8), 256, GEMM_SMEM>>>();
    k_stageC<<<N / 4, 256, SMEM_C>>>(f0, f1, f2, bias, y);
}

// round 10
// speedup vs baseline: 1.0294x; 1.0294x over previous
#include <cuda_runtime.h>
#include <cstdint>

// ---------------- static device scratch (no allocations allowed) ----------------
__device__ float g_T3[4096 * 512];      // 8 MB : in-contracted activations (tf32 bits)
__device__ float g_U [4096 * 512];      // 8 MB : core-contracted activations (fp32)
__device__ float g_coreTF[512 * 512];   // 1 MB : core pre-converted to tf32 bits

__device__ __forceinline__ uint32_t f2tf32(float f) {
    uint32_t u;
    asm("cvt.rna.tf32.f32 %0, %1;" : "=r"(u) : "f"(f));
    return u;
}
__device__ __forceinline__ uint32_t smem_u32(const void* p) {
    uint32_t a;
    asm("{ .reg .u64 t; cvta.to.shared.u64 t, %1; cvt.u32.u64 %0, t; }" : "=r"(a) : "l"(p));
    return a;
}
#define CP_ASYNC16(dst, src) \
    asm volatile("cp.async.cg.shared.global [%0], [%1], 16;" :: "r"(dst), "l"(src) : "memory")
#define CP_COMMIT() asm volatile("cp.async.commit_group;" ::: "memory")
#define CP_WAIT(n)  asm volatile("cp.async.wait_group %0;" :: "n"(n) : "memory")

// ---------------- K0: pre-convert core to tf32 bits ----------------
__global__ __launch_bounds__(256) void k_cvtcore(const float* __restrict__ core) {
    int i = (blockIdx.x * 256 + threadIdx.x) * 4;
    float4 v = *(const float4*)(core + i);
    uint4 o = make_uint4(f2tf32(v.x), f2tf32(v.y), f2tf32(v.z), f2tf32(v.w));
    *(uint4*)(g_coreTF + i) = o;
}

// ---------------- K1: stage A, warp-per-sample, vectorized x loads ----------------
static constexpr int T1L = 272;
static constexpr int T2L = 144;
static constexpr int WSM = 8 * T1L + 8 * T2L;               // 3328 floats / warp
static constexpr int SMEM_A = (8 * WSM + 384) * 4;          // 108032 B

__global__ __launch_bounds__(256, 2) void k_stageA(const float* __restrict__ x,
                                                   const float* __restrict__ f3,
                                                   const float* __restrict__ f4,
                                                   const float* __restrict__ f5) {
    extern __shared__ float sm[];
    float* f3s = sm + 8 * WSM;
    float* f4s = f3s + 128;
    float* f5s = f4s + 128;

    int t = threadIdx.x, wid = t >> 5, lane = t & 31;
    if (t < 128) { f3s[t] = f3[t]; f4s[t] = f4[t]; f5s[t] = f5[t]; }
    __syncthreads();

    float* t1w = sm + wid * WSM;
    float* t2w = t1w + 8 * T1L;

    long s = (long)blockIdx.x * 8 + wid;
    const float* xs = x + s * 4096;

    // ---- phase 1: float4 loads ----
    {
        float acc[2][4][8];   // [j][q][l]
#pragma unroll
        for (int j = 0; j < 2; j++)
#pragma unroll
            for (int q = 0; q < 4; q++)
#pragma unroll
                for (int l = 0; l < 8; l++) acc[j][q][l] = 0.f;
#pragma unroll 4
        for (int d = 0; d < 16; d++) {
            float4 xv0 = *(const float4*)(xs + d * 256 + 4 * lane);
            float4 xv1 = *(const float4*)(xs + d * 256 + 4 * lane + 128);
            float xv[2][4] = { {xv0.x, xv0.y, xv0.z, xv0.w},
                               {xv1.x, xv1.y, xv1.z, xv1.w} };
#pragma unroll
            for (int l = 0; l < 8; l++) {
                float fv = f3s[d * 8 + l];
#pragma unroll
                for (int j = 0; j < 2; j++)
#pragma unroll
                    for (int q = 0; q < 4; q++)
                        acc[j][q][l] += xv[j][q] * fv;
            }
        }
#pragma unroll
        for (int l = 0; l < 8; l++)
#pragma unroll
            for (int j = 0; j < 2; j++) {
                float4 v = make_float4(acc[j][0][l], acc[j][1][l],
                                       acc[j][2][l], acc[j][3][l]);
                *(float4*)(t1w + l * T1L + 4 * lane + 128 * j) = v;
            }
    }
    __syncwarp();

    // ---- phase 2 ----
    {
        float acc[4][8];
#pragma unroll
        for (int q = 0; q < 4; q++)
#pragma unroll
            for (int m = 0; m < 8; m++) acc[q][m] = 0.f;
#pragma unroll
        for (int e = 0; e < 16; e++) {
            float tv[4];
#pragma unroll
            for (int q = 0; q < 4; q++) {
                int p = lane + 32 * q, l = p >> 4, f = p & 15;
                tv[q] = t1w[l * T1L + e * 16 + f];
            }
#pragma unroll
            for (int m = 0; m < 8; m++) {
                float fv = f4s[e * 8 + m];
#pragma unroll
                for (int q = 0; q < 4; q++) acc[q][m] += tv[q] * fv;
            }
        }
#pragma unroll
        for (int q = 0; q < 4; q++) {
            int p = lane + 32 * q, l = p >> 4, f = p & 15;
#pragma unroll
            for (int m = 0; m < 8; m++)
                t2w[l * T2L + m * 17 + f] = acc[q][m];
        }
    }
    __syncwarp();

    // ---- phase 3 -> g_T3 (tf32 bits) ----
    {
#pragma unroll
        for (int h = 0; h < 2; h++) {
            int lm = lane + 32 * h, l = lm >> 3, m = lm & 7;
            float acc[8];
#pragma unroll
            for (int n = 0; n < 8; n++) acc[n] = 0.f;
#pragma unroll
            for (int f = 0; f < 16; f++) {
                float tv = t2w[l * T2L + m * 17 + f];
#pragma unroll
                for (int n = 0; n < 8; n++) acc[n] += tv * f5s[f * 8 + n];
            }
            uint4* dst = (uint4*)(g_T3 + s * 512 + lm * 8);
            dst[0] = make_uint4(f2tf32(acc[0]), f2tf32(acc[1]), f2tf32(acc[2]), f2tf32(acc[3]));
            dst[1] = make_uint4(f2tf32(acc[4]), f2tf32(acc[5]), f2tf32(acc[6]), f2tf32(acc[7]));
        }
    }
}

// ---------------- K2: stage B via mma.sync tf32, 512 threads, 3-deep pipeline (R8) ----------------
// 128x128 tile, 16 warps (4m x 4n), each warp 32x32. K chunks of 32.
static constexpr int GS = 36;
static constexpr int GEMM_SMEM = 6 * 128 * GS * 4;   // 110592 B

__global__ __launch_bounds__(512) void k_gemm_mma() {
    extern __shared__ float sm[];
    uint32_t sm_u = smem_u32(sm);

    int t = threadIdx.x;
    int lane = t & 31, wid = t >> 5;
    int warp_m = (wid & 3) * 32;
    int warp_n = (wid >> 2) * 32;
    long s0 = (long)blockIdx.x * 128;
    int n0 = blockIdx.y * 128;

    int i0 = t, i1 = t + 512;
    int r0 = i0 >> 3, c0v = (i0 & 7) * 4;
    int r1 = i1 >> 3, c1v = (i1 & 7) * 4;
    const float* AG0 = g_T3 + (s0 + r0) * 512 + c0v;
    const float* AG1 = g_T3 + (s0 + r1) * 512 + c1v;
    const float* BG0 = g_coreTF + (size_t)(n0 + r0) * 512 + c0v;
    const float* BG1 = g_coreTF + (size_t)(n0 + r1) * 512 + c1v;
    uint32_t d0 = (uint32_t)((r0 * GS + c0v) * 4);
    uint32_t d1 = (uint32_t)((r1 * GS + c1v) * 4);

    float acc[2][4][4];
#pragma unroll
    for (int mt = 0; mt < 2; mt++)
#pragma unroll
        for (int nt = 0; nt < 4; nt++)
#pragma unroll
            for (int i = 0; i < 4; i++) acc[mt][nt][i] = 0.f;

    int fr = lane >> 2, fc = lane & 3;

    // prologue: issue chunks 0,1
#pragma unroll
    for (int pc = 0; pc < 2; pc++) {
        uint32_t Au = sm_u + pc * 128 * GS * 4;
        uint32_t Bu = sm_u + (3 + pc) * 128 * GS * 4;
        CP_ASYNC16(Au + d0, AG0 + pc * 32);
        CP_ASYNC16(Au + d1, AG1 + pc * 32);
        CP_ASYNC16(Bu + d0, BG0 + pc * 32);
        CP_ASYNC16(Bu + d1, BG1 + pc * 32);
        CP_COMMIT();
    }

#pragma unroll 1
    for (int c = 0; c < 16; c++) {
        int p = c % 3;
        if (c == 15) { CP_WAIT(0); } else { CP_WAIT(1); }
        __syncthreads();

        const float* As = sm + p * 128 * GS;
        const float* Bs = sm + (3 + p) * 128 * GS;
#pragma unroll
        for (int ks = 0; ks < 4; ks++) {
            int k0 = ks * 8;
            uint32_t a[2][4], b[4][2];
#pragma unroll
            for (int mt = 0; mt < 2; mt++) {
                const float* ab = As + (warp_m + mt * 16 + fr) * GS + k0 + fc;
                a[mt][0] = __float_as_uint(ab[0]);
                a[mt][1] = __float_as_uint(ab[8 * GS]);
                a[mt][2] = __float_as_uint(ab[4]);
                a[mt][3] = __float_as_uint(ab[8 * GS + 4]);
            }
#pragma unroll
            for (int nt = 0; nt < 4; nt++) {
                const float* bb = Bs + (warp_n + nt * 8 + fr) * GS + k0 + fc;
                b[nt][0] = __float_as_uint(bb[0]);
                b[nt][1] = __float_as_uint(bb[4]);
            }
#pragma unroll
            for (int mt = 0; mt < 2; mt++)
#pragma unroll
                for (int nt = 0; nt < 4; nt++)
                    asm volatile(
                        "mma.sync.aligned.m16n8k8.row.col.f32.tf32.tf32.f32 "
                        "{%0,%1,%2,%3}, {%4,%5,%6,%7}, {%8,%9}, {%0,%1,%2,%3};"
                        : "+f"(acc[mt][nt][0]), "+f"(acc[mt][nt][1]),
                          "+f"(acc[mt][nt][2]), "+f"(acc[mt][nt][3])
                        : "r"(a[mt][0]), "r"(a[mt][1]), "r"(a[mt][2]), "r"(a[mt][3]),
                          "r"(b[nt][0]), "r"(b[nt][1]));
        }

        if (c + 2 < 16) {
            int pn = (c + 2) % 3;
            uint32_t Au = sm_u + pn * 128 * GS * 4;
            uint32_t Bu = sm_u + (3 + pn) * 128 * GS * 4;
            int off = (c + 2) * 32;
            CP_ASYNC16(Au + d0, AG0 + off);
            CP_ASYNC16(Au + d1, AG1 + off);
            CP_ASYNC16(Bu + d0, BG0 + off);
            CP_ASYNC16(Bu + d1, BG1 + off);
            CP_COMMIT();
        }
    }

    // epilogue
    int cp = (lane & 3) * 2;
#pragma unroll
    for (int mt = 0; mt < 2; mt++)
#pragma unroll
        for (int h = 0; h < 2; h++) {
            long m = s0 + warp_m + mt * 16 + fr + h * 8;
            float* dst = g_U + m * 512 + n0 + warp_n + cp;
#pragma unroll
            for (int nt = 0; nt < 4; nt++) {
                float2 v = make_float2(acc[mt][nt][h * 2], acc[mt][nt][h * 2 + 1]);
                *(float2*)(dst + nt * 8) = v;
            }
        }
}

// ---------------- K3: stage C (block version, 4 samples/block, 3 CTAs/SM) ----------------
__global__ __launch_bounds__(256, 3) void k_stageC(const float* __restrict__ f0,
                                                   const float* __restrict__ f1,
                                                   const float* __restrict__ f2,
                                                   const float* __restrict__ bias,
                                                   float* __restrict__ y) {
    extern __shared__ float sm[];
    float* u1s = sm;                    // 4 * 1152
    float* u2s = sm + 4 * 1152;         // 4 * 2176
    float* f0s = u2s + 4 * 2176;
    float* f1s = f0s + 128;
    float* f2s = f1s + 128;

    int t = threadIdx.x;
    if (t < 128) { f0s[t] = f0[t]; f1s[t] = f1[t]; f2s[t] = f2[t]; }
    __syncthreads();

    long s0 = (long)blockIdx.x * 4;

    {
        int g = t >> 6, jk = t & 63;
        float acc[4][4];
#pragma unroll
        for (int s = 0; s < 4; s++)
#pragma unroll
            for (int a4 = 0; a4 < 4; a4++) acc[s][a4] = 0.f;
#pragma unroll
        for (int i = 0; i < 8; i++) {
            float uv0 = g_U[(s0 + 0) * 512 + i * 64 + jk];
            float uv1 = g_U[(s0 + 1) * 512 + i * 64 + jk];
            float uv2 = g_U[(s0 + 2) * 512 + i * 64 + jk];
            float uv3 = g_U[(s0 + 3) * 512 + i * 64 + jk];
#pragma unroll
            for (int a4 = 0; a4 < 4; a4++) {
                float fv = f0s[(g * 4 + a4) * 8 + i];
                acc[0][a4] += uv0 * fv; acc[1][a4] += uv1 * fv;
                acc[2][a4] += uv2 * fv; acc[3][a4] += uv3 * fv;
            }
        }
#pragma unroll
        for (int s = 0; s < 4; s++)
#pragma unroll
            for (int a4 = 0; a4 < 4; a4++)
                u1s[s * 1152 + (g * 4 + a4) * 72 + jk] = acc[s][a4];
    }
    __syncthreads();

    {
        int h = t >> 7, pair = t & 127;
        int a = pair >> 3, k = pair & 7;
        float acc[2][16];
#pragma unroll
        for (int z = 0; z < 2; z++)
#pragma unroll
            for (int b = 0; b < 16; b++) acc[z][b] = 0.f;
#pragma unroll
        for (int j = 0; j < 8; j++) {
            float tv0 = u1s[(2 * h + 0) * 1152 + a * 72 + j * 8 + k];
            float tv1 = u1s[(2 * h + 1) * 1152 + a * 72 + j * 8 + k];
#pragma unroll
            for (int b = 0; b < 16; b++) {
                float fv = f1s[b * 8 + j];
                acc[0][b] += tv0 * fv; acc[1][b] += tv1 * fv;
            }
        }
#pragma unroll
        for (int z = 0; z < 2; z++)
#pragma unroll
            for (int b = 0; b < 16; b++)
                u2s[(2 * h + z) * 2176 + a * 136 + b * 8 + k] = acc[z][b];
    }
    __syncthreads();

    {
        int q = t & 3, ab0 = t >> 2;
#pragma unroll
        for (int r = 0; r < 4; r++) {
            int ab = ab0 + 64 * r;
            int a = ab >> 4, b = ab & 15;
            float acc[4][4];
#pragma unroll
            for (int s = 0; s < 4; s++)
#pragma unroll
                for (int c4 = 0; c4 < 4; c4++) acc[s][c4] = 0.f;
#pragma unroll
            for (int k = 0; k < 8; k++) {
                float tv0 = u2s[0 * 2176 + a * 136 + b * 8 + k];
                float tv1 = u2s[1 * 2176 + a * 136 + b * 8 + k];
                float tv2 = u2s[2 * 2176 + a * 136 + b * 8 + k];
                float tv3 = u2s[3 * 2176 + a * 136 + b * 8 + k];
#pragma unroll
                for (int c4 = 0; c4 < 4; c4++) {
                    float fv = f2s[(q * 4 + c4) * 8 + k];
                    acc[0][c4] += tv0 * fv; acc[1][c4] += tv1 * fv;
                    acc[2][c4] += tv2 * fv; acc[3][c4] += tv3 * fv;
                }
            }
            float4 bv = *(const float4*)&bias[ab * 16 + q * 4];
#pragma unroll
            for (int s = 0; s < 4; s++) {
                float4 o = make_float4(acc[s][0] + bv.x, acc[s][1] + bv.y,
                                       acc[s][2] + bv.z, acc[s][3] + bv.w);
                *(float4*)&y[(s0 + s) * 4096 + ab * 16 + q * 4] = o;
            }
        }
    }
}

// ---------------- launch ----------------
extern "C" void kernel_launch(void* const* d_in, const int* in_sizes, int n_in,
                              void* d_out, int out_size) {
    const float* x    = (const float*)d_in[0];
    const float* core = (const float*)d_in[1];
    const float* f0   = (const float*)d_in[2];
    const float* f1   = (const float*)d_in[3];
    const float* f2   = (const float*)d_in[4];
    const float* f3   = (const float*)d_in[5];
    const float* f4   = (const float*)d_in[6];
    const float* f5   = (const float*)d_in[7];
    const float* bias = (const float*)d_in[8];
    float* y = (float*)d_out;

    int N = in_sizes[0] / 4096;

    const int SMEM_C = (4 * 1152 + 4 * 2176 + 384) * 4;   // 54784

    cudaFuncSetAttribute(k_stageA, cudaFuncAttributeMaxDynamicSharedMemorySize, SMEM_A);
    cudaFuncSetAttribute(k_gemm_mma, cudaFuncAttributeMaxDynamicSharedMemorySize, GEMM_SMEM);
    cudaFuncSetAttribute(k_stageC, cudaFuncAttributeMaxDynamicSharedMemorySize, SMEM_C);

    k_cvtcore<<<256, 256>>>(core);
    k_stageA<<<N / 8, 256, SMEM_A>>>(x, f3, f4, f5);
    k_gemm_mma<<<dim3(N / 128, 4), 512, GEMM_SMEM>>>();
    k_stageC<<<N / 4, 256, SMEM_C>>>(f0, f1, f2, bias, y);
}

// round 11
// speedup vs baseline: 1.1018x; 1.0703x over previous
#include <cuda_runtime.h>
#include <cstdint>

// ---------------- static device scratch (no allocations allowed) ----------------
__device__ float g_T3[4096 * 512];      // 8 MB : in-contracted activations (tf32 bits)
__device__ float g_U [4096 * 512];      // 8 MB : core-contracted activations (fp32)
__device__ float g_coreTF[512 * 512];   // 1 MB : core pre-converted to tf32 bits

__device__ __forceinline__ uint32_t f2tf32(float f) {
    uint32_t u;
    asm("cvt.rna.tf32.f32 %0, %1;" : "=r"(u) : "f"(f));
    return u;
}
__device__ __forceinline__ uint32_t smem_u32(const void* p) {
    uint32_t a;
    asm("{ .reg .u64 t; cvta.to.shared.u64 t, %1; cvt.u32.u64 %0, t; }" : "=r"(a) : "l"(p));
    return a;
}
#define CP_ASYNC16(dst, src) \
    asm volatile("cp.async.cg.shared.global [%0], [%1], 16;" :: "r"(dst), "l"(src) : "memory")
#define CP_COMMIT() asm volatile("cp.async.commit_group;" ::: "memory")
#define CP_WAIT(n)  asm volatile("cp.async.wait_group %0;" :: "n"(n) : "memory")

// ---------------- K1: stage A, warp-per-sample + embedded core conversion ----------------
static constexpr int T1L = 272;
static constexpr int T2L = 144;
static constexpr int WSM = 8 * T1L + 8 * T2L;               // 3328 floats / warp
static constexpr int SMEM_A = (8 * WSM + 384) * 4;          // 108032 B

__global__ __launch_bounds__(256, 2) void k_stageA(const float* __restrict__ x,
                                                   const float* __restrict__ f3,
                                                   const float* __restrict__ f4,
                                                   const float* __restrict__ f5,
                                                   const float* __restrict__ core) {
    extern __shared__ float sm[];
    float* f3s = sm + 8 * WSM;
    float* f4s = f3s + 128;
    float* f5s = f4s + 128;

    int t = threadIdx.x, wid = t >> 5, lane = t & 31;
    // embedded core -> tf32 conversion (512 blocks x 512 floats = 512x512)
    if (t < 128) {
        int i = (blockIdx.x * 128 + t) * 4;
        float4 v = *(const float4*)(core + i);
        uint4 o = make_uint4(f2tf32(v.x), f2tf32(v.y), f2tf32(v.z), f2tf32(v.w));
        *(uint4*)(g_coreTF + i) = o;
        f3s[t] = f3[t]; f4s[t] = f4[t]; f5s[t] = f5[t];
    }
    __syncthreads();

    float* t1w = sm + wid * WSM;
    float* t2w = t1w + 8 * T1L;

    long s = (long)blockIdx.x * 8 + wid;
    const float* xs = x + s * 4096;

    // ---- phase 1: float4 loads for x and f3 ----
    {
        float acc[2][4][8];   // [j][q][l]
#pragma unroll
        for (int j = 0; j < 2; j++)
#pragma unroll
            for (int q = 0; q < 4; q++)
#pragma unroll
                for (int l = 0; l < 8; l++) acc[j][q][l] = 0.f;
#pragma unroll 4
        for (int d = 0; d < 16; d++) {
            float4 xv0 = *(const float4*)(xs + d * 256 + 4 * lane);
            float4 xv1 = *(const float4*)(xs + d * 256 + 4 * lane + 128);
            float xv[2][4] = { {xv0.x, xv0.y, xv0.z, xv0.w},
                               {xv1.x, xv1.y, xv1.z, xv1.w} };
            float4 fA = *(const float4*)(f3s + d * 8);
            float4 fB = *(const float4*)(f3s + d * 8 + 4);
            float fl[8] = { fA.x, fA.y, fA.z, fA.w, fB.x, fB.y, fB.z, fB.w };
#pragma unroll
            for (int l = 0; l < 8; l++)
#pragma unroll
                for (int j = 0; j < 2; j++)
#pragma unroll
                    for (int q = 0; q < 4; q++)
                        acc[j][q][l] += xv[j][q] * fl[l];
        }
#pragma unroll
        for (int l = 0; l < 8; l++)
#pragma unroll
            for (int j = 0; j < 2; j++) {
                float4 v = make_float4(acc[j][0][l], acc[j][1][l],
                                       acc[j][2][l], acc[j][3][l]);
                *(float4*)(t1w + l * T1L + 4 * lane + 128 * j) = v;
            }
    }
    __syncwarp();

    // ---- phase 2: float4 f4 loads ----
    {
        float acc[4][8];
#pragma unroll
        for (int q = 0; q < 4; q++)
#pragma unroll
            for (int m = 0; m < 8; m++) acc[q][m] = 0.f;
#pragma unroll
        for (int e = 0; e < 16; e++) {
            float tv[4];
#pragma unroll
            for (int q = 0; q < 4; q++) {
                int p = lane + 32 * q, l = p >> 4, f = p & 15;
                tv[q] = t1w[l * T1L + e * 16 + f];
            }
            float4 fA = *(const float4*)(f4s + e * 8);
            float4 fB = *(const float4*)(f4s + e * 8 + 4);
            float fm[8] = { fA.x, fA.y, fA.z, fA.w, fB.x, fB.y, fB.z, fB.w };
#pragma unroll
            for (int m = 0; m < 8; m++)
#pragma unroll
                for (int q = 0; q < 4; q++) acc[q][m] += tv[q] * fm[m];
        }
#pragma unroll
        for (int q = 0; q < 4; q++) {
            int p = lane + 32 * q, l = p >> 4, f = p & 15;
#pragma unroll
            for (int m = 0; m < 8; m++)
                t2w[l * T2L + m * 17 + f] = acc[q][m];
        }
    }
    __syncwarp();

    // ---- phase 3 -> g_T3 (tf32 bits), float4 f5 loads ----
    {
#pragma unroll
        for (int h = 0; h < 2; h++) {
            int lm = lane + 32 * h, l = lm >> 3, m = lm & 7;
            float acc[8];
#pragma unroll
            for (int n = 0; n < 8; n++) acc[n] = 0.f;
#pragma unroll
            for (int f = 0; f < 16; f++) {
                float tv = t2w[l * T2L + m * 17 + f];
                float4 fA = *(const float4*)(f5s + f * 8);
                float4 fB = *(const float4*)(f5s + f * 8 + 4);
                float fn[8] = { fA.x, fA.y, fA.z, fA.w, fB.x, fB.y, fB.z, fB.w };
#pragma unroll
                for (int n = 0; n < 8; n++) acc[n] += tv * fn[n];
            }
            uint4* dst = (uint4*)(g_T3 + s * 512 + lm * 8);
            dst[0] = make_uint4(f2tf32(acc[0]), f2tf32(acc[1]), f2tf32(acc[2]), f2tf32(acc[3]));
            dst[1] = make_uint4(f2tf32(acc[4]), f2tf32(acc[5]), f2tf32(acc[6]), f2tf32(acc[7]));
        }
    }
}

// ---------------- K2: stage B via mma.sync tf32, 512 threads, 3-deep pipeline (R8) ----------------
static constexpr int GS = 36;
static constexpr int GEMM_SMEM = 6 * 128 * GS * 4;   // 110592 B

__global__ __launch_bounds__(512) void k_gemm_mma() {
    extern __shared__ float sm[];
    uint32_t sm_u = smem_u32(sm);

    int t = threadIdx.x;
    int lane = t & 31, wid = t >> 5;
    int warp_m = (wid & 3) * 32;
    int warp_n = (wid >> 2) * 32;
    long s0 = (long)blockIdx.x * 128;
    int n0 = blockIdx.y * 128;

    int i0 = t, i1 = t + 512;
    int r0 = i0 >> 3, c0v = (i0 & 7) * 4;
    int r1 = i1 >> 3, c1v = (i1 & 7) * 4;
    const float* AG0 = g_T3 + (s0 + r0) * 512 + c0v;
    const float* AG1 = g_T3 + (s0 + r1) * 512 + c1v;
    const float* BG0 = g_coreTF + (size_t)(n0 + r0) * 512 + c0v;
    const float* BG1 = g_coreTF + (size_t)(n0 + r1) * 512 + c1v;
    uint32_t d0 = (uint32_t)((r0 * GS + c0v) * 4);
    uint32_t d1 = (uint32_t)((r1 * GS + c1v) * 4);

    float acc[2][4][4];
#pragma unroll
    for (int mt = 0; mt < 2; mt++)
#pragma unroll
        for (int nt = 0; nt < 4; nt++)
#pragma unroll
            for (int i = 0; i < 4; i++) acc[mt][nt][i] = 0.f;

    int fr = lane >> 2, fc = lane & 3;

#pragma unroll
    for (int pc = 0; pc < 2; pc++) {
        uint32_t Au = sm_u + pc * 128 * GS * 4;
        uint32_t Bu = sm_u + (3 + pc) * 128 * GS * 4;
        CP_ASYNC16(Au + d0, AG0 + pc * 32);
        CP_ASYNC16(Au + d1, AG1 + pc * 32);
        CP_ASYNC16(Bu + d0, BG0 + pc * 32);
        CP_ASYNC16(Bu + d1, BG1 + pc * 32);
        CP_COMMIT();
    }

#pragma unroll 1
    for (int c = 0; c < 16; c++) {
        int p = c % 3;
        if (c == 15) { CP_WAIT(0); } else { CP_WAIT(1); }
        __syncthreads();

        const float* As = sm + p * 128 * GS;
        const float* Bs = sm + (3 + p) * 128 * GS;
#pragma unroll
        for (int ks = 0; ks < 4; ks++) {
            int k0 = ks * 8;
            uint32_t a[2][4], b[4][2];
#pragma unroll
            for (int mt = 0; mt < 2; mt++) {
                const float* ab = As + (warp_m + mt * 16 + fr) * GS + k0 + fc;
                a[mt][0] = __float_as_uint(ab[0]);
                a[mt][1] = __float_as_uint(ab[8 * GS]);
                a[mt][2] = __float_as_uint(ab[4]);
                a[mt][3] = __float_as_uint(ab[8 * GS + 4]);
            }
#pragma unroll
            for (int nt = 0; nt < 4; nt++) {
                const float* bb = Bs + (warp_n + nt * 8 + fr) * GS + k0 + fc;
                b[nt][0] = __float_as_uint(bb[0]);
                b[nt][1] = __float_as_uint(bb[4]);
            }
#pragma unroll
            for (int mt = 0; mt < 2; mt++)
#pragma unroll
                for (int nt = 0; nt < 4; nt++)
                    asm volatile(
                        "mma.sync.aligned.m16n8k8.row.col.f32.tf32.tf32.f32 "
                        "{%0,%1,%2,%3}, {%4,%5,%6,%7}, {%8,%9}, {%0,%1,%2,%3};"
                        : "+f"(acc[mt][nt][0]), "+f"(acc[mt][nt][1]),
                          "+f"(acc[mt][nt][2]), "+f"(acc[mt][nt][3])
                        : "r"(a[mt][0]), "r"(a[mt][1]), "r"(a[mt][2]), "r"(a[mt][3]),
                          "r"(b[nt][0]), "r"(b[nt][1]));
        }

        if (c + 2 < 16) {
            int pn = (c + 2) % 3;
            uint32_t Au = sm_u + pn * 128 * GS * 4;
            uint32_t Bu = sm_u + (3 + pn) * 128 * GS * 4;
            int off = (c + 2) * 32;
            CP_ASYNC16(Au + d0, AG0 + off);
            CP_ASYNC16(Au + d1, AG1 + off);
            CP_ASYNC16(Bu + d0, BG0 + off);
            CP_ASYNC16(Bu + d1, BG1 + off);
            CP_COMMIT();
        }
    }

    int cp = (lane & 3) * 2;
#pragma unroll
    for (int mt = 0; mt < 2; mt++)
#pragma unroll
        for (int h = 0; h < 2; h++) {
            long m = s0 + warp_m + mt * 16 + fr + h * 8;
            float* dst = g_U + m * 512 + n0 + warp_n + cp;
#pragma unroll
            for (int nt = 0; nt < 4; nt++) {
                float2 v = make_float2(acc[mt][nt][h * 2], acc[mt][nt][h * 2 + 1]);
                *(float2*)(dst + nt * 8) = v;
            }
        }
}

// ---------------- K3: stage C (block version, transposed factors for LDS.128) ----------------
__global__ __launch_bounds__(256, 3) void k_stageC(const float* __restrict__ f0,
                                                   const float* __restrict__ f1,
                                                   const float* __restrict__ f2,
                                                   const float* __restrict__ bias,
                                                   float* __restrict__ y) {
    extern __shared__ float sm[];
    float* u1s = sm;                    // 4 * 1152
    float* u2s = sm + 4 * 1152;         // 4 * 2176
    float* f0t = u2s + 4 * 2176;        // transposed: f0t[i*16+a]
    float* f1t = f0t + 128;             // f1t[j*16+b]
    float* f2t = f1t + 128;             // f2t[k*16+c]

    int t = threadIdx.x;
    if (t < 128) {
        int rr = t >> 3, cc = t & 7;    // source row (out-dim), col (rank)
        f0t[cc * 16 + rr] = f0[t];
        f1t[cc * 16 + rr] = f1[t];
        f2t[cc * 16 + rr] = f2[t];
    }
    __syncthreads();

    long s0 = (long)blockIdx.x * 4;

    // ---- phase 1: u1 ----
    {
        int g = t >> 6, jk = t & 63;
        float acc[4][4];
#pragma unroll
        for (int s = 0; s < 4; s++)
#pragma unroll
            for (int a4 = 0; a4 < 4; a4++) acc[s][a4] = 0.f;
#pragma unroll
        for (int i = 0; i < 8; i++) {
            float uv0 = g_U[(s0 + 0) * 512 + i * 64 + jk];
            float uv1 = g_U[(s0 + 1) * 512 + i * 64 + jk];
            float uv2 = g_U[(s0 + 2) * 512 + i * 64 + jk];
            float uv3 = g_U[(s0 + 3) * 512 + i * 64 + jk];
            float4 fv = *(const float4*)(f0t + i * 16 + g * 4);
            float fa[4] = { fv.x, fv.y, fv.z, fv.w };
#pragma unroll
            for (int a4 = 0; a4 < 4; a4++) {
                acc[0][a4] += uv0 * fa[a4]; acc[1][a4] += uv1 * fa[a4];
                acc[2][a4] += uv2 * fa[a4]; acc[3][a4] += uv3 * fa[a4];
            }
        }
#pragma unroll
        for (int s = 0; s < 4; s++)
#pragma unroll
            for (int a4 = 0; a4 < 4; a4++)
                u1s[s * 1152 + (g * 4 + a4) * 72 + jk] = acc[s][a4];
    }
    __syncthreads();

    // ---- phase 2: u2 ----
    {
        int h = t >> 7, pair = t & 127;
        int a = pair >> 3, k = pair & 7;
        float acc[2][16];
#pragma unroll
        for (int z = 0; z < 2; z++)
#pragma unroll
            for (int b = 0; b < 16; b++) acc[z][b] = 0.f;
#pragma unroll
        for (int j = 0; j < 8; j++) {
            float tv0 = u1s[(2 * h + 0) * 1152 + a * 72 + j * 8 + k];
            float tv1 = u1s[(2 * h + 1) * 1152 + a * 72 + j * 8 + k];
            float4 g0 = *(const float4*)(f1t + j * 16);
            float4 g1 = *(const float4*)(f1t + j * 16 + 4);
            float4 g2 = *(const float4*)(f1t + j * 16 + 8);
            float4 g3 = *(const float4*)(f1t + j * 16 + 12);
            float fb[16] = { g0.x, g0.y, g0.z, g0.w, g1.x, g1.y, g1.z, g1.w,
                             g2.x, g2.y, g2.z, g2.w, g3.x, g3.y, g3.z, g3.w };
#pragma unroll
            for (int b = 0; b < 16; b++) {
                acc[0][b] += tv0 * fb[b]; acc[1][b] += tv1 * fb[b];
            }
        }
#pragma unroll
        for (int z = 0; z < 2; z++)
#pragma unroll
            for (int b = 0; b < 16; b++)
                u2s[(2 * h + z) * 2176 + a * 136 + b * 8 + k] = acc[z][b];
    }
    __syncthreads();

    // ---- phase 3: y ----
    {
        int q = t & 3, ab0 = t >> 2;
#pragma unroll
        for (int r = 0; r < 4; r++) {
            int ab = ab0 + 64 * r;
            int a = ab >> 4, b = ab & 15;
            float acc[4][4];
#pragma unroll
            for (int s = 0; s < 4; s++)
#pragma unroll
                for (int c4 = 0; c4 < 4; c4++) acc[s][c4] = 0.f;
#pragma unroll
            for (int k = 0; k < 8; k++) {
                float tv0 = u2s[0 * 2176 + a * 136 + b * 8 + k];
                float tv1 = u2s[1 * 2176 + a * 136 + b * 8 + k];
                float tv2 = u2s[2 * 2176 + a * 136 + b * 8 + k];
                float tv3 = u2s[3 * 2176 + a * 136 + b * 8 + k];
                float4 fv = *(const float4*)(f2t + k * 16 + q * 4);
                float fc[4] = { fv.x, fv.y, fv.z, fv.w };
#pragma unroll
                for (int c4 = 0; c4 < 4; c4++) {
                    acc[0][c4] += tv0 * fc[c4]; acc[1][c4] += tv1 * fc[c4];
                    acc[2][c4] += tv2 * fc[c4]; acc[3][c4] += tv3 * fc[c4];
                }
            }
            float4 bv = *(const float4*)&bias[ab * 16 + q * 4];
#pragma unroll
            for (int s = 0; s < 4; s++) {
                float4 o = make_float4(acc[s][0] + bv.x, acc[s][1] + bv.y,
                                       acc[s][2] + bv.z, acc[s][3] + bv.w);
                *(float4*)&y[(s0 + s) * 4096 + ab * 16 + q * 4] = o;
            }
        }
    }
}

// ---------------- launch ----------------
extern "C" void kernel_launch(void* const* d_in, const int* in_sizes, int n_in,
                              void* d_out, int out_size) {
    const float* x    = (const float*)d_in[0];
    const float* core = (const float*)d_in[1];
    const float* f0   = (const float*)d_in[2];
    const float* f1   = (const float*)d_in[3];
    const float* f2   = (const float*)d_in[4];
    const float* f3   = (const float*)d_in[5];
    const float* f4   = (const float*)d_in[6];
    const float* f5   = (const float*)d_in[7];
    const float* bias = (const float*)d_in[8];
    float* y = (float*)d_out;

    int N = in_sizes[0] / 4096;

    const int SMEM_C = (4 * 1152 + 4 * 2176 + 384) * 4;   // 54784

    cudaFuncSetAttribute(k_stageA, cudaFuncAttributeMaxDynamicSharedMemorySize, SMEM_A);
    cudaFuncSetAttribute(k_gemm_mma, cudaFuncAttributeMaxDynamicSharedMemorySize, GEMM_SMEM);
    cudaFuncSetAttribute(k_stageC, cudaFuncAttributeMaxDynamicSharedMemorySize, SMEM_C);

    k_stageA<<<N / 8, 256, SMEM_A>>>(x, f3, f4, f5, core);
    k_gemm_mma<<<dim3(N / 128, 4), 512, GEMM_SMEM>>>();
    k_stageC<<<N / 4, 256, SMEM_C>>>(f0, f1, f2, bias, y);
}

// round 12
// speedup vs baseline: 1.1029x; 1.0010x over previous
#include <cuda_runtime.h>
#include <cstdint>

// ---------------- static device scratch (no allocations allowed) ----------------
__device__ float g_T3[4096 * 512];      // 8 MB : in-contracted activations (tf32 bits)
__device__ float g_U [4096 * 512];      // 8 MB : core-contracted activations (fp32)
__device__ float g_coreTF[512 * 512];   // 1 MB : core pre-converted to tf32 bits

__device__ __forceinline__ uint32_t f2tf32(float f) {
    uint32_t u;
    asm("cvt.rna.tf32.f32 %0, %1;" : "=r"(u) : "f"(f));
    return u;
}
__device__ __forceinline__ uint32_t smem_u32(const void* p) {
    uint32_t a;
    asm("{ .reg .u64 t; cvta.to.shared.u64 t, %1; cvt.u32.u64 %0, t; }" : "=r"(a) : "l"(p));
    return a;
}
#define CP_ASYNC16(dst, src) \
    asm volatile("cp.async.cg.shared.global [%0], [%1], 16;" :: "r"(dst), "l"(src) : "memory")
#define CP_COMMIT() asm volatile("cp.async.commit_group;" ::: "memory")
#define CP_WAIT(n)  asm volatile("cp.async.wait_group %0;" :: "n"(n) : "memory")

// ---------------- K1: stage A, warp-per-sample + embedded core conversion ----------------
static constexpr int T1L = 272;
static constexpr int T2L = 144;
static constexpr int WSM = 8 * T1L + 8 * T2L;               // 3328 floats / warp
static constexpr int SMEM_A = (8 * WSM + 384) * 4;          // 108032 B

__global__ __launch_bounds__(256, 2) void k_stageA(const float* __restrict__ x,
                                                   const float* __restrict__ f3,
                                                   const float* __restrict__ f4,
                                                   const float* __restrict__ f5,
                                                   const float* __restrict__ core) {
    extern __shared__ float sm[];
    float* f3s = sm + 8 * WSM;
    float* f4s = f3s + 128;
    float* f5s = f4s + 128;

    int t = threadIdx.x, wid = t >> 5, lane = t & 31;
    if (t < 128) {
        int i = (blockIdx.x * 128 + t) * 4;
        float4 v = *(const float4*)(core + i);
        uint4 o = make_uint4(f2tf32(v.x), f2tf32(v.y), f2tf32(v.z), f2tf32(v.w));
        *(uint4*)(g_coreTF + i) = o;
        f3s[t] = f3[t]; f4s[t] = f4[t]; f5s[t] = f5[t];
    }
    __syncthreads();

    float* t1w = sm + wid * WSM;
    float* t2w = t1w + 8 * T1L;

    long s = (long)blockIdx.x * 8 + wid;
    const float* xs = x + s * 4096;

    // ---- phase 1 ----
    {
        float acc[2][4][8];
#pragma unroll
        for (int j = 0; j < 2; j++)
#pragma unroll
            for (int q = 0; q < 4; q++)
#pragma unroll
                for (int l = 0; l < 8; l++) acc[j][q][l] = 0.f;
#pragma unroll 4
        for (int d = 0; d < 16; d++) {
            float4 xv0 = *(const float4*)(xs + d * 256 + 4 * lane);
            float4 xv1 = *(const float4*)(xs + d * 256 + 4 * lane + 128);
            float xv[2][4] = { {xv0.x, xv0.y, xv0.z, xv0.w},
                               {xv1.x, xv1.y, xv1.z, xv1.w} };
            float4 fA = *(const float4*)(f3s + d * 8);
            float4 fB = *(const float4*)(f3s + d * 8 + 4);
            float fl[8] = { fA.x, fA.y, fA.z, fA.w, fB.x, fB.y, fB.z, fB.w };
#pragma unroll
            for (int l = 0; l < 8; l++)
#pragma unroll
                for (int j = 0; j < 2; j++)
#pragma unroll
                    for (int q = 0; q < 4; q++)
                        acc[j][q][l] += xv[j][q] * fl[l];
        }
#pragma unroll
        for (int l = 0; l < 8; l++)
#pragma unroll
            for (int j = 0; j < 2; j++) {
                float4 v = make_float4(acc[j][0][l], acc[j][1][l],
                                       acc[j][2][l], acc[j][3][l]);
                *(float4*)(t1w + l * T1L + 4 * lane + 128 * j) = v;
            }
    }
    __syncwarp();

    // ---- phase 2 ----
    {
        float acc[4][8];
#pragma unroll
        for (int q = 0; q < 4; q++)
#pragma unroll
            for (int m = 0; m < 8; m++) acc[q][m] = 0.f;
#pragma unroll
        for (int e = 0; e < 16; e++) {
            float tv[4];
#pragma unroll
            for (int q = 0; q < 4; q++) {
                int p = lane + 32 * q, l = p >> 4, f = p & 15;
                tv[q] = t1w[l * T1L + e * 16 + f];
            }
            float4 fA = *(const float4*)(f4s + e * 8);
            float4 fB = *(const float4*)(f4s + e * 8 + 4);
            float fm[8] = { fA.x, fA.y, fA.z, fA.w, fB.x, fB.y, fB.z, fB.w };
#pragma unroll
            for (int m = 0; m < 8; m++)
#pragma unroll
                for (int q = 0; q < 4; q++) acc[q][m] += tv[q] * fm[m];
        }
#pragma unroll
        for (int q = 0; q < 4; q++) {
            int p = lane + 32 * q, l = p >> 4, f = p & 15;
#pragma unroll
            for (int m = 0; m < 8; m++)
                t2w[l * T2L + m * 17 + f] = acc[q][m];
        }
    }
    __syncwarp();

    // ---- phase 3 -> g_T3 (tf32 bits) ----
    {
#pragma unroll
        for (int h = 0; h < 2; h++) {
            int lm = lane + 32 * h, l = lm >> 3, m = lm & 7;
            float acc[8];
#pragma unroll
            for (int n = 0; n < 8; n++) acc[n] = 0.f;
#pragma unroll
            for (int f = 0; f < 16; f++) {
                float tv = t2w[l * T2L + m * 17 + f];
                float4 fA = *(const float4*)(f5s + f * 8);
                float4 fB = *(const float4*)(f5s + f * 8 + 4);
                float fn[8] = { fA.x, fA.y, fA.z, fA.w, fB.x, fB.y, fB.z, fB.w };
#pragma unroll
                for (int n = 0; n < 8; n++) acc[n] += tv * fn[n];
            }
            uint4* dst = (uint4*)(g_T3 + s * 512 + lm * 8);
            dst[0] = make_uint4(f2tf32(acc[0]), f2tf32(acc[1]), f2tf32(acc[2]), f2tf32(acc[3]));
            dst[1] = make_uint4(f2tf32(acc[4]), f2tf32(acc[5]), f2tf32(acc[6]), f2tf32(acc[7]));
        }
    }
}

// ---------------- K2: stage B via mma.sync tf32, 512 threads, K-chunk 64, 3-stage ----------------
// 128x128 tile, 16 warps (4m x 4n), each warp 32x32. K in 8 chunks of 64.
static constexpr int GS = 68;                         // 64 + 4 pad words
static constexpr int OP_ST = 128 * GS;                // words per operand stage
static constexpr int GEMM_SMEM = 6 * OP_ST * 4;       // 208896 B (3 stages x 2 operands)

__global__ __launch_bounds__(512) void k_gemm_mma() {
    extern __shared__ float sm[];
    uint32_t sm_u = smem_u32(sm);

    int t = threadIdx.x;
    int lane = t & 31, wid = t >> 5;
    int warp_m = (wid & 3) * 32;
    int warp_n = (wid >> 2) * 32;
    long s0 = (long)blockIdx.x * 128;
    int n0 = blockIdx.y * 128;

    // per-chunk loads: 4 float4 per thread per operand (128 rows x 16 float4)
    int rr[4], cc[4];
#pragma unroll
    for (int i = 0; i < 4; i++) {
        int ii = t + 512 * i;
        rr[i] = ii >> 4;            // row 0..127
        cc[i] = (ii & 15) * 4;      // col 0..60 step 4
    }
    const float* AGp[4]; const float* BGp[4]; uint32_t Sd[4];
#pragma unroll
    for (int i = 0; i < 4; i++) {
        AGp[i] = g_T3 + (s0 + rr[i]) * 512 + cc[i];
        BGp[i] = g_coreTF + (size_t)(n0 + rr[i]) * 512 + cc[i];
        Sd[i] = (uint32_t)((rr[i] * GS + cc[i]) * 4);
    }

    float acc[2][4][4];
#pragma unroll
    for (int mt = 0; mt < 2; mt++)
#pragma unroll
        for (int nt = 0; nt < 4; nt++)
#pragma unroll
            for (int i = 0; i < 4; i++) acc[mt][nt][i] = 0.f;

    int fr = lane >> 2, fc = lane & 3;

    // prologue: issue chunks 0,1 (K offsets 0,64)
#pragma unroll
    for (int pc = 0; pc < 2; pc++) {
        uint32_t Au = sm_u + (2 * pc) * OP_ST * 4;
        uint32_t Bu = sm_u + (2 * pc + 1) * OP_ST * 4;
#pragma unroll
        for (int i = 0; i < 4; i++) {
            CP_ASYNC16(Au + Sd[i], AGp[i] + pc * 64);
            CP_ASYNC16(Bu + Sd[i], BGp[i] + pc * 64);
        }
        CP_COMMIT();
    }

#pragma unroll 1
    for (int c = 0; c < 8; c++) {
        int p = c % 3;
        if (c == 7) { CP_WAIT(0); } else { CP_WAIT(1); }
        __syncthreads();

        const float* As = sm + (2 * p) * OP_ST;
        const float* Bs = sm + (2 * p + 1) * OP_ST;
#pragma unroll
        for (int ks = 0; ks < 8; ks++) {
            int k0 = ks * 8;
            uint32_t a[2][4], b[4][2];
#pragma unroll
            for (int mt = 0; mt < 2; mt++) {
                const float* ab = As + (warp_m + mt * 16 + fr) * GS + k0 + fc;
                a[mt][0] = __float_as_uint(ab[0]);
                a[mt][1] = __float_as_uint(ab[8 * GS]);
                a[mt][2] = __float_as_uint(ab[4]);
                a[mt][3] = __float_as_uint(ab[8 * GS + 4]);
            }
#pragma unroll
            for (int nt = 0; nt < 4; nt++) {
                const float* bb = Bs + (warp_n + nt * 8 + fr) * GS + k0 + fc;
                b[nt][0] = __float_as_uint(bb[0]);
                b[nt][1] = __float_as_uint(bb[4]);
            }
#pragma unroll
            for (int mt = 0; mt < 2; mt++)
#pragma unroll
                for (int nt = 0; nt < 4; nt++)
                    asm volatile(
                        "mma.sync.aligned.m16n8k8.row.col.f32.tf32.tf32.f32 "
                        "{%0,%1,%2,%3}, {%4,%5,%6,%7}, {%8,%9}, {%0,%1,%2,%3};"
                        : "+f"(acc[mt][nt][0]), "+f"(acc[mt][nt][1]),
                          "+f"(acc[mt][nt][2]), "+f"(acc[mt][nt][3])
                        : "r"(a[mt][0]), "r"(a[mt][1]), "r"(a[mt][2]), "r"(a[mt][3]),
                          "r"(b[nt][0]), "r"(b[nt][1]));
        }

        if (c + 2 < 8) {
            int pn = (c + 2) % 3;
            uint32_t Au = sm_u + (2 * pn) * OP_ST * 4;
            uint32_t Bu = sm_u + (2 * pn + 1) * OP_ST * 4;
            int off = (c + 2) * 64;
#pragma unroll
            for (int i = 0; i < 4; i++) {
                CP_ASYNC16(Au + Sd[i], AGp[i] + off);
                CP_ASYNC16(Bu + Sd[i], BGp[i] + off);
            }
            CP_COMMIT();
        }
    }

    // epilogue
    int cp = (lane & 3) * 2;
#pragma unroll
    for (int mt = 0; mt < 2; mt++)
#pragma unroll
        for (int h = 0; h < 2; h++) {
            long m = s0 + warp_m + mt * 16 + fr + h * 8;
            float* dst = g_U + m * 512 + n0 + warp_n + cp;
#pragma unroll
            for (int nt = 0; nt < 4; nt++) {
                float2 v = make_float2(acc[mt][nt][h * 2], acc[mt][nt][h * 2 + 1]);
                *(float2*)(dst + nt * 8) = v;
            }
        }
}

// ---------------- K3: stage C (block version, transposed factors for LDS.128) ----------------
__global__ __launch_bounds__(256, 3) void k_stageC(const float* __restrict__ f0,
                                                   const float* __restrict__ f1,
                                                   const float* __restrict__ f2,
                                                   const float* __restrict__ bias,
                                                   float* __restrict__ y) {
    extern __shared__ float sm[];
    float* u1s = sm;                    // 4 * 1152
    float* u2s = sm + 4 * 1152;         // 4 * 2176
    float* f0t = u2s + 4 * 2176;
    float* f1t = f0t + 128;
    float* f2t = f1t + 128;

    int t = threadIdx.x;
    if (t < 128) {
        int rr = t >> 3, cc = t & 7;
        f0t[cc * 16 + rr] = f0[t];
        f1t[cc * 16 + rr] = f1[t];
        f2t[cc * 16 + rr] = f2[t];
    }
    __syncthreads();

    long s0 = (long)blockIdx.x * 4;

    {
        int g = t >> 6, jk = t & 63;
        float acc[4][4];
#pragma unroll
        for (int s = 0; s < 4; s++)
#pragma unroll
            for (int a4 = 0; a4 < 4; a4++) acc[s][a4] = 0.f;
#pragma unroll
        for (int i = 0; i < 8; i++) {
            float uv0 = g_U[(s0 + 0) * 512 + i * 64 + jk];
            float uv1 = g_U[(s0 + 1) * 512 + i * 64 + jk];
            float uv2 = g_U[(s0 + 2) * 512 + i * 64 + jk];
            float uv3 = g_U[(s0 + 3) * 512 + i * 64 + jk];
            float4 fv = *(const float4*)(f0t + i * 16 + g * 4);
            float fa[4] = { fv.x, fv.y, fv.z, fv.w };
#pragma unroll
            for (int a4 = 0; a4 < 4; a4++) {
                acc[0][a4] += uv0 * fa[a4]; acc[1][a4] += uv1 * fa[a4];
                acc[2][a4] += uv2 * fa[a4]; acc[3][a4] += uv3 * fa[a4];
            }
        }
#pragma unroll
        for (int s = 0; s < 4; s++)
#pragma unroll
            for (int a4 = 0; a4 < 4; a4++)
                u1s[s * 1152 + (g * 4 + a4) * 72 + jk] = acc[s][a4];
    }
    __syncthreads();

    {
        int h = t >> 7, pair = t & 127;
        int a = pair >> 3, k = pair & 7;
        float acc[2][16];
#pragma unroll
        for (int z = 0; z < 2; z++)
#pragma unroll
            for (int b = 0; b < 16; b++) acc[z][b] = 0.f;
#pragma unroll
        for (int j = 0; j < 8; j++) {
            float tv0 = u1s[(2 * h + 0) * 1152 + a * 72 + j * 8 + k];
            float tv1 = u1s[(2 * h + 1) * 1152 + a * 72 + j * 8 + k];
            float4 g0 = *(const float4*)(f1t + j * 16);
            float4 g1 = *(const float4*)(f1t + j * 16 + 4);
            float4 g2 = *(const float4*)(f1t + j * 16 + 8);
            float4 g3 = *(const float4*)(f1t + j * 16 + 12);
            float fb[16] = { g0.x, g0.y, g0.z, g0.w, g1.x, g1.y, g1.z, g1.w,
                             g2.x, g2.y, g2.z, g2.w, g3.x, g3.y, g3.z, g3.w };
#pragma unroll
            for (int b = 0; b < 16; b++) {
                acc[0][b] += tv0 * fb[b]; acc[1][b] += tv1 * fb[b];
            }
        }
#pragma unroll
        for (int z = 0; z < 2; z++)
#pragma unroll
            for (int b = 0; b < 16; b++)
                u2s[(2 * h + z) * 2176 + a * 136 + b * 8 + k] = acc[z][b];
    }
    __syncthreads();

    {
        int q = t & 3, ab0 = t >> 2;
#pragma unroll
        for (int r = 0; r < 4; r++) {
            int ab = ab0 + 64 * r;
            int a = ab >> 4, b = ab & 15;
            float acc[4][4];
#pragma unroll
            for (int s = 0; s < 4; s++)
#pragma unroll
                for (int c4 = 0; c4 < 4; c4++) acc[s][c4] = 0.f;
#pragma unroll
            for (int k = 0; k < 8; k++) {
                float tv0 = u2s[0 * 2176 + a * 136 + b * 8 + k];
                float tv1 = u2s[1 * 2176 + a * 136 + b * 8 + k];
                float tv2 = u2s[2 * 2176 + a * 136 + b * 8 + k];
                float tv3 = u2s[3 * 2176 + a * 136 + b * 8 + k];
                float4 fv = *(const float4*)(f2t + k * 16 + q * 4);
                float fcv[4] = { fv.x, fv.y, fv.z, fv.w };
#pragma unroll
                for (int c4 = 0; c4 < 4; c4++) {
                    acc[0][c4] += tv0 * fcv[c4]; acc[1][c4] += tv1 * fcv[c4];
                    acc[2][c4] += tv2 * fcv[c4]; acc[3][c4] += tv3 * fcv[c4];
                }
            }
            float4 bv = *(const float4*)&bias[ab * 16 + q * 4];
#pragma unroll
            for (int s = 0; s < 4; s++) {
                float4 o = make_float4(acc[s][0] + bv.x, acc[s][1] + bv.y,
                                       acc[s][2] + bv.z, acc[s][3] + bv.w);
                *(float4*)&y[(s0 + s) * 4096 + ab * 16 + q * 4] = o;
            }
        }
    }
}

// ---------------- launch ----------------
extern "C" void kernel_launch(void* const* d_in, const int* in_sizes, int n_in,
                              void* d_out, int out_size) {
    const float* x    = (const float*)d_in[0];
    const float* core = (const float*)d_in[1];
    const float* f0   = (const float*)d_in[2];
    const float* f1   = (const float*)d_in[3];
    const float* f2   = (const float*)d_in[4];
    const float* f3   = (const float*)d_in[5];
    const float* f4   = (const float*)d_in[6];
    const float* f5   = (const float*)d_in[7];
    const float* bias = (const float*)d_in[8];
    float* y = (float*)d_out;

    int N = in_sizes[0] / 4096;

    const int SMEM_C = (4 * 1152 + 4 * 2176 + 384) * 4;   // 54784

    cudaFuncSetAttribute(k_stageA, cudaFuncAttributeMaxDynamicSharedMemorySize, SMEM_A);
    cudaFuncSetAttribute(k_gemm_mma, cudaFuncAttributeMaxDynamicSharedMemorySize, GEMM_SMEM);
    cudaFuncSetAttribute(k_stageC, cudaFuncAttributeMaxDynamicSharedMemorySize, SMEM_C);

    k_stageA<<<N / 8, 256, SMEM_A>>>(x, f3, f4, f5, core);
    k_gemm_mma<<<dim3(N / 128, 4), 512, GEMM_SMEM>>>();
    k_stageC<<<N / 4, 256, SMEM_C>>>(f0, f1, f2, bias, y);
}

// round 13
// speedup vs baseline: 1.1654x; 1.0567x over previous
#include <cuda_runtime.h>
#include <cstdint>

// ---------------- static device scratch (no allocations allowed) ----------------
__device__ float g_T3[4096 * 512];      // 8 MB : in-contracted activations (tf32 bits)
__device__ float g_U [4096 * 512];      // 8 MB : core-contracted activations (fp32)
__device__ float g_coreTF[512 * 512];   // 1 MB : core pre-converted to tf32 bits

__device__ __forceinline__ uint32_t f2tf32(float f) {
    uint32_t u;
    asm("cvt.rna.tf32.f32 %0, %1;" : "=r"(u) : "f"(f));
    return u;
}
__device__ __forceinline__ uint32_t smem_u32(const void* p) {
    uint32_t a;
    asm("{ .reg .u64 t; cvta.to.shared.u64 t, %1; cvt.u32.u64 %0, t; }" : "=r"(a) : "l"(p));
    return a;
}
#define CP_ASYNC16(dst, src) \
    asm volatile("cp.async.cg.shared.global [%0], [%1], 16;" :: "r"(dst), "l"(src) : "memory")
#define CP_COMMIT() asm volatile("cp.async.commit_group;" ::: "memory")
#define CP_WAIT(n)  asm volatile("cp.async.wait_group %0;" :: "n"(n) : "memory")

// ---------------- K1: stage A — 2 warps/sample, t2 overlays t1, 32 warps/SM ----------------
// Block: 128 threads (4 warps) = 2 samples. Phase layout per sample (region = 8*272 floats):
//   t1[l, ef]   stride T1L=272              (phase 1 out, phase 2 in)
//   t2[l, m, f] strides 144/17, OVERLAID on t1 after phase-2 reads complete
static constexpr int T1L = 272;
static constexpr int SAMP = 8 * T1L;                        // 2176 floats / sample
static constexpr int SMEM_A = (2 * SAMP + 384) * 4;         // 18944 B

__global__ __launch_bounds__(128, 8) void k_stageA(const float* __restrict__ x,
                                                   const float* __restrict__ f3,
                                                   const float* __restrict__ f4,
                                                   const float* __restrict__ f5,
                                                   const float* __restrict__ core) {
    extern __shared__ float sm[];
    float* f3s = sm + 2 * SAMP;
    float* f4s = f3s + 128;
    float* f5s = f4s + 128;

    int t = threadIdx.x, wid = t >> 5, lane = t & 31;
    int sid = wid >> 1, half = wid & 1;

    // embedded core -> tf32 conversion: 2048 blocks x 128 floats
    if (t < 32) {
        int i = (blockIdx.x * 32 + t) * 4;
        float4 v = *(const float4*)(core + i);
        uint4 o = make_uint4(f2tf32(v.x), f2tf32(v.y), f2tf32(v.z), f2tf32(v.w));
        *(uint4*)(g_coreTF + i) = o;
    }
    f3s[t] = f3[t]; f4s[t] = f4[t]; f5s[t] = f5[t];
    __syncthreads();

    float* t1s = sm + sid * SAMP;
    long s = (long)blockIdx.x * 2 + sid;
    const float* xs = x + s * 4096 + half * 128 + 4 * lane;

    // ---- phase 1: t1[l, ef] = sum_d x[d, ef] * f3[d, l]  (this warp: 128 ef cols) ----
    {
        float acc[4][8];   // [q][l], ef = half*128 + 4*lane + q
#pragma unroll
        for (int q = 0; q < 4; q++)
#pragma unroll
            for (int l = 0; l < 8; l++) acc[q][l] = 0.f;
#pragma unroll 4
        for (int d = 0; d < 16; d++) {
            float4 xv = *(const float4*)(xs + d * 256);
            float4 fA = *(const float4*)(f3s + d * 8);
            float4 fB = *(const float4*)(f3s + d * 8 + 4);
            float fl[8] = { fA.x, fA.y, fA.z, fA.w, fB.x, fB.y, fB.z, fB.w };
#pragma unroll
            for (int l = 0; l < 8; l++) {
                acc[0][l] += xv.x * fl[l]; acc[1][l] += xv.y * fl[l];
                acc[2][l] += xv.z * fl[l]; acc[3][l] += xv.w * fl[l];
            }
        }
#pragma unroll
        for (int l = 0; l < 8; l++) {
            float4 v = make_float4(acc[0][l], acc[1][l], acc[2][l], acc[3][l]);
            *(float4*)(t1s + l * T1L + half * 128 + 4 * lane) = v;
        }
    }
    __syncthreads();

    // ---- phase 2: t2[l,m,f] = sum_e t1[l, e*16+f] * f4[e,m]  (2 (l,f) pairs per lane) ----
    {
        float acc[2][8];
#pragma unroll
        for (int z = 0; z < 2; z++)
#pragma unroll
            for (int m = 0; m < 8; m++) acc[z][m] = 0.f;
#pragma unroll
        for (int e = 0; e < 16; e++) {
            float tv[2];
#pragma unroll
            for (int z = 0; z < 2; z++) {
                int p = half * 64 + 32 * z + lane, l = p >> 4, f = p & 15;
                tv[z] = t1s[l * T1L + e * 16 + f];
            }
            float4 fA = *(const float4*)(f4s + e * 8);
            float4 fB = *(const float4*)(f4s + e * 8 + 4);
            float fm[8] = { fA.x, fA.y, fA.z, fA.w, fB.x, fB.y, fB.z, fB.w };
#pragma unroll
            for (int m = 0; m < 8; m++)
#pragma unroll
                for (int z = 0; z < 2; z++) acc[z][m] += tv[z] * fm[m];
        }
        __syncthreads();   // all t1 reads complete before overlay writes
#pragma unroll
        for (int z = 0; z < 2; z++) {
            int p = half * 64 + 32 * z + lane, l = p >> 4, f = p & 15;
#pragma unroll
            for (int m = 0; m < 8; m++)
                t1s[l * 144 + m * 17 + f] = acc[z][m];   // t2 overlay
        }
    }
    __syncthreads();

    // ---- phase 3: t3[lm*8+n] = sum_f t2[l,m,f] * f5[f,n]  (1 (l,m) pair per lane) ----
    {
        int lm = half * 32 + lane, l = lm >> 3, m = lm & 7;
        float acc[8];
#pragma unroll
        for (int n = 0; n < 8; n++) acc[n] = 0.f;
#pragma unroll
        for (int f = 0; f < 16; f++) {
            float tv = t1s[l * 144 + m * 17 + f];
            float4 fA = *(const float4*)(f5s + f * 8);
            float4 fB = *(const float4*)(f5s + f * 8 + 4);
            float fn[8] = { fA.x, fA.y, fA.z, fA.w, fB.x, fB.y, fB.z, fB.w };
#pragma unroll
            for (int n = 0; n < 8; n++) acc[n] += tv * fn[n];
        }
        uint4* dst = (uint4*)(g_T3 + s * 512 + lm * 8);
        dst[0] = make_uint4(f2tf32(acc[0]), f2tf32(acc[1]), f2tf32(acc[2]), f2tf32(acc[3]));
        dst[1] = make_uint4(f2tf32(acc[4]), f2tf32(acc[5]), f2tf32(acc[6]), f2tf32(acc[7]));
    }
}

// ---------------- K2: stage B via mma.sync tf32, 512 threads, K-chunk 64, 3-stage ----------------
static constexpr int GS = 68;
static constexpr int OP_ST = 128 * GS;
static constexpr int GEMM_SMEM = 6 * OP_ST * 4;       // 208896 B

__global__ __launch_bounds__(512) void k_gemm_mma() {
    extern __shared__ float sm[];
    uint32_t sm_u = smem_u32(sm);

    int t = threadIdx.x;
    int lane = t & 31, wid = t >> 5;
    int warp_m = (wid & 3) * 32;
    int warp_n = (wid >> 2) * 32;
    long s0 = (long)blockIdx.x * 128;
    int n0 = blockIdx.y * 128;

    int rr[4], cc[4];
#pragma unroll
    for (int i = 0; i < 4; i++) {
        int ii = t + 512 * i;
        rr[i] = ii >> 4;
        cc[i] = (ii & 15) * 4;
    }
    const float* AGp[4]; const float* BGp[4]; uint32_t Sd[4];
#pragma unroll
    for (int i = 0; i < 4; i++) {
        AGp[i] = g_T3 + (s0 + rr[i]) * 512 + cc[i];
        BGp[i] = g_coreTF + (size_t)(n0 + rr[i]) * 512 + cc[i];
        Sd[i] = (uint32_t)((rr[i] * GS + cc[i]) * 4);
    }

    float acc[2][4][4];
#pragma unroll
    for (int mt = 0; mt < 2; mt++)
#pragma unroll
        for (int nt = 0; nt < 4; nt++)
#pragma unroll
            for (int i = 0; i < 4; i++) acc[mt][nt][i] = 0.f;

    int fr = lane >> 2, fc = lane & 3;

#pragma unroll
    for (int pc = 0; pc < 2; pc++) {
        uint32_t Au = sm_u + (2 * pc) * OP_ST * 4;
        uint32_t Bu = sm_u + (2 * pc + 1) * OP_ST * 4;
#pragma unroll
        for (int i = 0; i < 4; i++) {
            CP_ASYNC16(Au + Sd[i], AGp[i] + pc * 64);
            CP_ASYNC16(Bu + Sd[i], BGp[i] + pc * 64);
        }
        CP_COMMIT();
    }

#pragma unroll 1
    for (int c = 0; c < 8; c++) {
        int p = c % 3;
        if (c == 7) { CP_WAIT(0); } else { CP_WAIT(1); }
        __syncthreads();

        const float* As = sm + (2 * p) * OP_ST;
        const float* Bs = sm + (2 * p + 1) * OP_ST;
#pragma unroll
        for (int ks = 0; ks < 8; ks++) {
            int k0 = ks * 8;
            uint32_t a[2][4], b[4][2];
#pragma unroll
            for (int mt = 0; mt < 2; mt++) {
                const float* ab = As + (warp_m + mt * 16 + fr) * GS + k0 + fc;
                a[mt][0] = __float_as_uint(ab[0]);
                a[mt][1] = __float_as_uint(ab[8 * GS]);
                a[mt][2] = __float_as_uint(ab[4]);
                a[mt][3] = __float_as_uint(ab[8 * GS + 4]);
            }
#pragma unroll
            for (int nt = 0; nt < 4; nt++) {
                const float* bb = Bs + (warp_n + nt * 8 + fr) * GS + k0 + fc;
                b[nt][0] = __float_as_uint(bb[0]);
                b[nt][1] = __float_as_uint(bb[4]);
            }
#pragma unroll
            for (int mt = 0; mt < 2; mt++)
#pragma unroll
                for (int nt = 0; nt < 4; nt++)
                    asm volatile(
                        "mma.sync.aligned.m16n8k8.row.col.f32.tf32.tf32.f32 "
                        "{%0,%1,%2,%3}, {%4,%5,%6,%7}, {%8,%9}, {%0,%1,%2,%3};"
                        : "+f"(acc[mt][nt][0]), "+f"(acc[mt][nt][1]),
                          "+f"(acc[mt][nt][2]), "+f"(acc[mt][nt][3])
                        : "r"(a[mt][0]), "r"(a[mt][1]), "r"(a[mt][2]), "r"(a[mt][3]),
                          "r"(b[nt][0]), "r"(b[nt][1]));
        }

        if (c + 2 < 8) {
            int pn = (c + 2) % 3;
            uint32_t Au = sm_u + (2 * pn) * OP_ST * 4;
            uint32_t Bu = sm_u + (2 * pn + 1) * OP_ST * 4;
            int off = (c + 2) * 64;
#pragma unroll
            for (int i = 0; i < 4; i++) {
                CP_ASYNC16(Au + Sd[i], AGp[i] + off);
                CP_ASYNC16(Bu + Sd[i], BGp[i] + off);
            }
            CP_COMMIT();
        }
    }

    int cp = (lane & 3) * 2;
#pragma unroll
    for (int mt = 0; mt < 2; mt++)
#pragma unroll
        for (int h = 0; h < 2; h++) {
            long m = s0 + warp_m + mt * 16 + fr + h * 8;
            float* dst = g_U + m * 512 + n0 + warp_n + cp;
#pragma unroll
            for (int nt = 0; nt < 4; nt++) {
                float2 v = make_float2(acc[mt][nt][h * 2], acc[mt][nt][h * 2 + 1]);
                *(float2*)(dst + nt * 8) = v;
            }
        }
}

// ---------------- K3: stage C (block version, transposed factors for LDS.128) ----------------
__global__ __launch_bounds__(256, 3) void k_stageC(const float* __restrict__ f0,
                                                   const float* __restrict__ f1,
                                                   const float* __restrict__ f2,
                                                   const float* __restrict__ bias,
                                                   float* __restrict__ y) {
    extern __shared__ float sm[];
    float* u1s = sm;                    // 4 * 1152
    float* u2s = sm + 4 * 1152;         // 4 * 2176
    float* f0t = u2s + 4 * 2176;
    float* f1t = f0t + 128;
    float* f2t = f1t + 128;

    int t = threadIdx.x;
    if (t < 128) {
        int rr = t >> 3, cc = t & 7;
        f0t[cc * 16 + rr] = f0[t];
        f1t[cc * 16 + rr] = f1[t];
        f2t[cc * 16 + rr] = f2[t];
    }
    __syncthreads();

    long s0 = (long)blockIdx.x * 4;

    {
        int g = t >> 6, jk = t & 63;
        float acc[4][4];
#pragma unroll
        for (int s = 0; s < 4; s++)
#pragma unroll
            for (int a4 = 0; a4 < 4; a4++) acc[s][a4] = 0.f;
#pragma unroll
        for (int i = 0; i < 8; i++) {
            float uv0 = g_U[(s0 + 0) * 512 + i * 64 + jk];
            float uv1 = g_U[(s0 + 1) * 512 + i * 64 + jk];
            float uv2 = g_U[(s0 + 2) * 512 + i * 64 + jk];
            float uv3 = g_U[(s0 + 3) * 512 + i * 64 + jk];
            float4 fv = *(const float4*)(f0t + i * 16 + g * 4);
            float fa[4] = { fv.x, fv.y, fv.z, fv.w };
#pragma unroll
            for (int a4 = 0; a4 < 4; a4++) {
                acc[0][a4] += uv0 * fa[a4]; acc[1][a4] += uv1 * fa[a4];
                acc[2][a4] += uv2 * fa[a4]; acc[3][a4] += uv3 * fa[a4];
            }
        }
#pragma unroll
        for (int s = 0; s < 4; s++)
#pragma unroll
            for (int a4 = 0; a4 < 4; a4++)
                u1s[s * 1152 + (g * 4 + a4) * 72 + jk] = acc[s][a4];
    }
    __syncthreads();

    {
        int h = t >> 7, pair = t & 127;
        int a = pair >> 3, k = pair & 7;
        float acc[2][16];
#pragma unroll
        for (int z = 0; z < 2; z++)
#pragma unroll
            for (int b = 0; b < 16; b++) acc[z][b] = 0.f;
#pragma unroll
        for (int j = 0; j < 8; j++) {
            float tv0 = u1s[(2 * h + 0) * 1152 + a * 72 + j * 8 + k];
            float tv1 = u1s[(2 * h + 1) * 1152 + a * 72 + j * 8 + k];
            float4 g0 = *(const float4*)(f1t + j * 16);
            float4 g1 = *(const float4*)(f1t + j * 16 + 4);
            float4 g2 = *(const float4*)(f1t + j * 16 + 8);
            float4 g3 = *(const float4*)(f1t + j * 16 + 12);
            float fb[16] = { g0.x, g0.y, g0.z, g0.w, g1.x, g1.y, g1.z, g1.w,
                             g2.x, g2.y, g2.z, g2.w, g3.x, g3.y, g3.z, g3.w };
#pragma unroll
            for (int b = 0; b < 16; b++) {
                acc[0][b] += tv0 * fb[b]; acc[1][b] += tv1 * fb[b];
            }
        }
#pragma unroll
        for (int z = 0; z < 2; z++)
#pragma unroll
            for (int b = 0; b < 16; b++)
                u2s[(2 * h + z) * 2176 + a * 136 + b * 8 + k] = acc[z][b];
    }
    __syncthreads();

    {
        int q = t & 3, ab0 = t >> 2;
#pragma unroll
        for (int r = 0; r < 4; r++) {
            int ab = ab0 + 64 * r;
            int a = ab >> 4, b = ab & 15;
            float acc[4][4];
#pragma unroll
            for (int s = 0; s < 4; s++)
#pragma unroll
                for (int c4 = 0; c4 < 4; c4++) acc[s][c4] = 0.f;
#pragma unroll
            for (int k = 0; k < 8; k++) {
                float tv0 = u2s[0 * 2176 + a * 136 + b * 8 + k];
                float tv1 = u2s[1 * 2176 + a * 136 + b * 8 + k];
                float tv2 = u2s[2 * 2176 + a * 136 + b * 8 + k];
                float tv3 = u2s[3 * 2176 + a * 136 + b * 8 + k];
                float4 fv = *(const float4*)(f2t + k * 16 + q * 4);
                float fcv[4] = { fv.x, fv.y, fv.z, fv.w };
#pragma unroll
                for (int c4 = 0; c4 < 4; c4++) {
                    acc[0][c4] += tv0 * fcv[c4]; acc[1][c4] += tv1 * fcv[c4];
                    acc[2][c4] += tv2 * fcv[c4]; acc[3][c4] += tv3 * fcv[c4];
                }
            }
            float4 bv = *(const float4*)&bias[ab * 16 + q * 4];
#pragma unroll
            for (int s = 0; s < 4; s++) {
                float4 o = make_float4(acc[s][0] + bv.x, acc[s][1] + bv.y,
                                       acc[s][2] + bv.z, acc[s][3] + bv.w);
                *(float4*)&y[(s0 + s) * 4096 + ab * 16 + q * 4] = o;
            }
        }
    }
}

// ---------------- launch ----------------
extern "C" void kernel_launch(void* const* d_in, const int* in_sizes, int n_in,
                              void* d_out, int out_size) {
    const float* x    = (const float*)d_in[0];
    const float* core = (const float*)d_in[1];
    const float* f0   = (const float*)d_in[2];
    const float* f1   = (const float*)d_in[3];
    const float* f2   = (const float*)d_in[4];
    const float* f3   = (const float*)d_in[5];
    const float* f4   = (const float*)d_in[6];
    const float* f5   = (const float*)d_in[7];
    const float* bias = (const float*)d_in[8];
    float* y = (float*)d_out;

    int N = in_sizes[0] / 4096;

    const int SMEM_C = (4 * 1152 + 4 * 2176 + 384) * 4;   // 54784

    cudaFuncSetAttribute(k_stageA, cudaFuncAttributeMaxDynamicSharedMemorySize, SMEM_A);
    cudaFuncSetAttribute(k_gemm_mma, cudaFuncAttributeMaxDynamicSharedMemorySize, GEMM_SMEM);
    cudaFuncSetAttribute(k_stageC, cudaFuncAttributeMaxDynamicSharedMemorySize, SMEM_C);

    k_stageA<<<N / 2, 128, SMEM_A>>>(x, f3, f4, f5, core);
    k_gemm_mma<<<dim3(N / 128, 4), 512, GEMM_SMEM>>>();
    k_stageC<<<N / 4, 256, SMEM_C>>>(f0, f1, f2, bias, y);
}

// round 14
// speedup vs baseline: 1.3549x; 1.1626x over previous
#include <cuda_runtime.h>
#include <cuda_fp16.h>
#include <cstdint>

// ---------------- static device scratch (no allocations allowed) ----------------
__device__ __half g_T3h[4096 * 512];    // 4 MB : in-contracted activations (fp16)
__device__ float  g_U  [4096 * 512];    // 8 MB : core-contracted activations (fp32)
__device__ __half g_coreH[512 * 512];   // 0.5 MB : core pre-converted to fp16

__device__ __forceinline__ uint32_t smem_u32(const void* p) {
    uint32_t a;
    asm("{ .reg .u64 t; cvta.to.shared.u64 t, %1; cvt.u32.u64 %0, t; }" : "=r"(a) : "l"(p));
    return a;
}
__device__ __forceinline__ uint32_t pack_h2(float a, float b) {
    __half2 h = __floats2half2_rn(a, b);
    return *(uint32_t*)&h;
}
#define CP_ASYNC16(dst, src) \
    asm volatile("cp.async.cg.shared.global [%0], [%1], 16;" :: "r"(dst), "l"(src) : "memory")
#define CP_COMMIT() asm volatile("cp.async.commit_group;" ::: "memory")
#define CP_WAIT(n)  asm volatile("cp.async.wait_group %0;" :: "n"(n) : "memory")

// ---------------- K1: stage A — 2 warps/sample, t2 overlays t1, fp16 output ----------------
static constexpr int T1L = 272;
static constexpr int SAMP = 8 * T1L;                        // 2176 floats / sample
static constexpr int SMEM_A = (2 * SAMP + 384) * 4;         // 18944 B

__global__ __launch_bounds__(128, 8) void k_stageA(const float* __restrict__ x,
                                                   const float* __restrict__ f3,
                                                   const float* __restrict__ f4,
                                                   const float* __restrict__ f5,
                                                   const float* __restrict__ core) {
    extern __shared__ float sm[];
    float* f3s = sm + 2 * SAMP;
    float* f4s = f3s + 128;
    float* f5s = f4s + 128;

    int t = threadIdx.x, wid = t >> 5, lane = t & 31;
    int sid = wid >> 1, half = wid & 1;

    // embedded core -> fp16 conversion: 2048 blocks x 128 floats
    if (t < 32) {
        int i = (blockIdx.x * 32 + t) * 4;
        float4 v = *(const float4*)(core + i);
        uint2 o = make_uint2(pack_h2(v.x, v.y), pack_h2(v.z, v.w));
        *(uint2*)(g_coreH + i) = o;
    }
    f3s[t] = f3[t]; f4s[t] = f4[t]; f5s[t] = f5[t];
    __syncthreads();

    float* t1s = sm + sid * SAMP;
    long s = (long)blockIdx.x * 2 + sid;
    const float* xs = x + s * 4096 + half * 128 + 4 * lane;

    // ---- phase 1 ----
    {
        float acc[4][8];
#pragma unroll
        for (int q = 0; q < 4; q++)
#pragma unroll
            for (int l = 0; l < 8; l++) acc[q][l] = 0.f;
#pragma unroll 4
        for (int d = 0; d < 16; d++) {
            float4 xv = *(const float4*)(xs + d * 256);
            float4 fA = *(const float4*)(f3s + d * 8);
            float4 fB = *(const float4*)(f3s + d * 8 + 4);
            float fl[8] = { fA.x, fA.y, fA.z, fA.w, fB.x, fB.y, fB.z, fB.w };
#pragma unroll
            for (int l = 0; l < 8; l++) {
                acc[0][l] += xv.x * fl[l]; acc[1][l] += xv.y * fl[l];
                acc[2][l] += xv.z * fl[l]; acc[3][l] += xv.w * fl[l];
            }
        }
#pragma unroll
        for (int l = 0; l < 8; l++) {
            float4 v = make_float4(acc[0][l], acc[1][l], acc[2][l], acc[3][l]);
            *(float4*)(t1s + l * T1L + half * 128 + 4 * lane) = v;
        }
    }
    __syncthreads();

    // ---- phase 2 (t2 overlays t1 after reads drain) ----
    {
        float acc[2][8];
#pragma unroll
        for (int z = 0; z < 2; z++)
#pragma unroll
            for (int m = 0; m < 8; m++) acc[z][m] = 0.f;
#pragma unroll
        for (int e = 0; e < 16; e++) {
            float tv[2];
#pragma unroll
            for (int z = 0; z < 2; z++) {
                int p = half * 64 + 32 * z + lane, l = p >> 4, f = p & 15;
                tv[z] = t1s[l * T1L + e * 16 + f];
            }
            float4 fA = *(const float4*)(f4s + e * 8);
            float4 fB = *(const float4*)(f4s + e * 8 + 4);
            float fm[8] = { fA.x, fA.y, fA.z, fA.w, fB.x, fB.y, fB.z, fB.w };
#pragma unroll
            for (int m = 0; m < 8; m++)
#pragma unroll
                for (int z = 0; z < 2; z++) acc[z][m] += tv[z] * fm[m];
        }
        __syncthreads();
#pragma unroll
        for (int z = 0; z < 2; z++) {
            int p = half * 64 + 32 * z + lane, l = p >> 4, f = p & 15;
#pragma unroll
            for (int m = 0; m < 8; m++)
                t1s[l * 144 + m * 17 + f] = acc[z][m];
        }
    }
    __syncthreads();

    // ---- phase 3 -> g_T3h (fp16) ----
    {
        int lm = half * 32 + lane, l = lm >> 3, m = lm & 7;
        float acc[8];
#pragma unroll
        for (int n = 0; n < 8; n++) acc[n] = 0.f;
#pragma unroll
        for (int f = 0; f < 16; f++) {
            float tv = t1s[l * 144 + m * 17 + f];
            float4 fA = *(const float4*)(f5s + f * 8);
            float4 fB = *(const float4*)(f5s + f * 8 + 4);
            float fn[8] = { fA.x, fA.y, fA.z, fA.w, fB.x, fB.y, fB.z, fB.w };
#pragma unroll
            for (int n = 0; n < 8; n++) acc[n] += tv * fn[n];
        }
        uint4 o = make_uint4(pack_h2(acc[0], acc[1]), pack_h2(acc[2], acc[3]),
                             pack_h2(acc[4], acc[5]), pack_h2(acc[6], acc[7]));
        *(uint4*)(g_T3h + s * 512 + lm * 8) = o;
    }
}

// ---------------- K2: stage B via mma.sync fp16 (m16n8k16), 512 threads, 3-stage ----------------
// 128x128 tile, 16 warps (4m x 4n), each warp 32x32. K in 8 chunks of 64 halfs.
// smem: rows of 64 halfs (32 words) padded to GS=36 words.
static constexpr int GS = 36;                         // words per row
static constexpr int OP_ST = 128 * GS;                // words per operand stage
static constexpr int GEMM_SMEM = 6 * OP_ST * 4;       // 110592 B

__global__ __launch_bounds__(512) void k_gemm_mma() {
    extern __shared__ float sm[];
    uint32_t sm_u = smem_u32(sm);

    int t = threadIdx.x;
    int lane = t & 31, wid = t >> 5;
    int warp_m = (wid & 3) * 32;
    int warp_n = (wid >> 2) * 32;
    long s0 = (long)blockIdx.x * 128;
    int n0 = blockIdx.y * 128;

    // per-chunk loads: 2 x 16B per thread per operand (128 rows x 8 segs)
    int rr[2], sg[2];
#pragma unroll
    for (int i = 0; i < 2; i++) {
        int ii = t + 512 * i;
        rr[i] = ii >> 3;            // row 0..127
        sg[i] = ii & 7;             // 16B segment in row (8 halfs each)
    }
    const __half* AGp[2]; const __half* BGp[2]; uint32_t Sd[2];
#pragma unroll
    for (int i = 0; i < 2; i++) {
        AGp[i] = g_T3h + (s0 + rr[i]) * 512 + sg[i] * 8;
        BGp[i] = g_coreH + (size_t)(n0 + rr[i]) * 512 + sg[i] * 8;
        Sd[i] = (uint32_t)((rr[i] * GS + sg[i] * 4) * 4);
    }

    float acc[2][4][4];
#pragma unroll
    for (int mt = 0; mt < 2; mt++)
#pragma unroll
        for (int nt = 0; nt < 4; nt++)
#pragma unroll
            for (int i = 0; i < 4; i++) acc[mt][nt][i] = 0.f;

    int fr = lane >> 2, fc = lane & 3;

    // prologue: issue chunks 0,1
#pragma unroll
    for (int pc = 0; pc < 2; pc++) {
        uint32_t Au = sm_u + (2 * pc) * OP_ST * 4;
        uint32_t Bu = sm_u + (2 * pc + 1) * OP_ST * 4;
#pragma unroll
        for (int i = 0; i < 2; i++) {
            CP_ASYNC16(Au + Sd[i], AGp[i] + pc * 64);
            CP_ASYNC16(Bu + Sd[i], BGp[i] + pc * 64);
        }
        CP_COMMIT();
    }

#pragma unroll 1
    for (int c = 0; c < 8; c++) {
        int p = c % 3;
        if (c == 7) { CP_WAIT(0); } else { CP_WAIT(1); }
        __syncthreads();

        const float* As = sm + (2 * p) * OP_ST;
        const float* Bs = sm + (2 * p + 1) * OP_ST;
#pragma unroll
        for (int ks = 0; ks < 4; ks++) {
            int k0 = ks * 8;   // word offset: 16 halfs per ks
            uint32_t a[2][4], b[4][2];
#pragma unroll
            for (int mt = 0; mt < 2; mt++) {
                const float* ab = As + (warp_m + mt * 16 + fr) * GS + k0 + fc;
                a[mt][0] = __float_as_uint(ab[0]);
                a[mt][1] = __float_as_uint(ab[8 * GS]);
                a[mt][2] = __float_as_uint(ab[4]);
                a[mt][3] = __float_as_uint(ab[8 * GS + 4]);
            }
#pragma unroll
            for (int nt = 0; nt < 4; nt++) {
                const float* bb = Bs + (warp_n + nt * 8 + fr) * GS + k0 + fc;
                b[nt][0] = __float_as_uint(bb[0]);
                b[nt][1] = __float_as_uint(bb[4]);
            }
#pragma unroll
            for (int mt = 0; mt < 2; mt++)
#pragma unroll
                for (int nt = 0; nt < 4; nt++)
                    asm volatile(
                        "mma.sync.aligned.m16n8k16.row.col.f32.f16.f16.f32 "
                        "{%0,%1,%2,%3}, {%4,%5,%6,%7}, {%8,%9}, {%0,%1,%2,%3};"
                        : "+f"(acc[mt][nt][0]), "+f"(acc[mt][nt][1]),
                          "+f"(acc[mt][nt][2]), "+f"(acc[mt][nt][3])
                        : "r"(a[mt][0]), "r"(a[mt][1]), "r"(a[mt][2]), "r"(a[mt][3]),
                          "r"(b[nt][0]), "r"(b[nt][1]));
        }

        if (c + 2 < 8) {
            int pn = (c + 2) % 3;
            uint32_t Au = sm_u + (2 * pn) * OP_ST * 4;
            uint32_t Bu = sm_u + (2 * pn + 1) * OP_ST * 4;
            int off = (c + 2) * 64;
#pragma unroll
            for (int i = 0; i < 2; i++) {
                CP_ASYNC16(Au + Sd[i], AGp[i] + off);
                CP_ASYNC16(Bu + Sd[i], BGp[i] + off);
            }
            CP_COMMIT();
        }
    }

    // epilogue (fp32 accumulators)
    int cp = (lane & 3) * 2;
#pragma unroll
    for (int mt = 0; mt < 2; mt++)
#pragma unroll
        for (int h = 0; h < 2; h++) {
            long m = s0 + warp_m + mt * 16 + fr + h * 8;
            float* dst = g_U + m * 512 + n0 + warp_n + cp;
#pragma unroll
            for (int nt = 0; nt < 4; nt++) {
                float2 v = make_float2(acc[mt][nt][h * 2], acc[mt][nt][h * 2 + 1]);
                *(float2*)(dst + nt * 8) = v;
            }
        }
}

// ---------------- K3: stage C (block version, transposed factors for LDS.128) ----------------
__global__ __launch_bounds__(256, 3) void k_stageC(const float* __restrict__ f0,
                                                   const float* __restrict__ f1,
                                                   const float* __restrict__ f2,
                                                   const float* __restrict__ bias,
                                                   float* __restrict__ y) {
    extern __shared__ float sm[];
    float* u1s = sm;                    // 4 * 1152
    float* u2s = sm + 4 * 1152;         // 4 * 2176
    float* f0t = u2s + 4 * 2176;
    float* f1t = f0t + 128;
    float* f2t = f1t + 128;

    int t = threadIdx.x;
    if (t < 128) {
        int rr = t >> 3, cc = t & 7;
        f0t[cc * 16 + rr] = f0[t];
        f1t[cc * 16 + rr] = f1[t];
        f2t[cc * 16 + rr] = f2[t];
    }
    __syncthreads();

    long s0 = (long)blockIdx.x * 4;

    {
        int g = t >> 6, jk = t & 63;
        float acc[4][4];
#pragma unroll
        for (int s = 0; s < 4; s++)
#pragma unroll
            for (int a4 = 0; a4 < 4; a4++) acc[s][a4] = 0.f;
#pragma unroll
        for (int i = 0; i < 8; i++) {
            float uv0 = g_U[(s0 + 0) * 512 + i * 64 + jk];
            float uv1 = g_U[(s0 + 1) * 512 + i * 64 + jk];
            float uv2 = g_U[(s0 + 2) * 512 + i * 64 + jk];
            float uv3 = g_U[(s0 + 3) * 512 + i * 64 + jk];
            float4 fv = *(const float4*)(f0t + i * 16 + g * 4);
            float fa[4] = { fv.x, fv.y, fv.z, fv.w };
#pragma unroll
            for (int a4 = 0; a4 < 4; a4++) {
                acc[0][a4] += uv0 * fa[a4]; acc[1][a4] += uv1 * fa[a4];
                acc[2][a4] += uv2 * fa[a4]; acc[3][a4] += uv3 * fa[a4];
            }
        }
#pragma unroll
        for (int s = 0; s < 4; s++)
#pragma unroll
            for (int a4 = 0; a4 < 4; a4++)
                u1s[s * 1152 + (g * 4 + a4) * 72 + jk] = acc[s][a4];
    }
    __syncthreads();

    {
        int h = t >> 7, pair = t & 127;
        int a = pair >> 3, k = pair & 7;
        float acc[2][16];
#pragma unroll
        for (int z = 0; z < 2; z++)
#pragma unroll
            for (int b = 0; b < 16; b++) acc[z][b] = 0.f;
#pragma unroll
        for (int j = 0; j < 8; j++) {
            float tv0 = u1s[(2 * h + 0) * 1152 + a * 72 + j * 8 + k];
            float tv1 = u1s[(2 * h + 1) * 1152 + a * 72 + j * 8 + k];
            float4 g0 = *(const float4*)(f1t + j * 16);
            float4 g1 = *(const float4*)(f1t + j * 16 + 4);
            float4 g2 = *(const float4*)(f1t + j * 16 + 8);
            float4 g3 = *(const float4*)(f1t + j * 16 + 12);
            float fb[16] = { g0.x, g0.y, g0.z, g0.w, g1.x, g1.y, g1.z, g1.w,
                             g2.x, g2.y, g2.z, g2.w, g3.x, g3.y, g3.z, g3.w };
#pragma unroll
            for (int b = 0; b < 16; b++) {
                acc[0][b] += tv0 * fb[b]; acc[1][b] += tv1 * fb[b];
            }
        }
#pragma unroll
        for (int z = 0; z < 2; z++)
#pragma unroll
            for (int b = 0; b < 16; b++)
                u2s[(2 * h + z) * 2176 + a * 136 + b * 8 + k] = acc[z][b];
    }
    __syncthreads();

    {
        int q = t & 3, ab0 = t >> 2;
#pragma unroll
        for (int r = 0; r < 4; r++) {
            int ab = ab0 + 64 * r;
            int a = ab >> 4, b = ab & 15;
            float acc[4][4];
#pragma unroll
            for (int s = 0; s < 4; s++)
#pragma unroll
                for (int c4 = 0; c4 < 4; c4++) acc[s][c4] = 0.f;
#pragma unroll
            for (int k = 0; k < 8; k++) {
                float tv0 = u2s[0 * 2176 + a * 136 + b * 8 + k];
                float tv1 = u2s[1 * 2176 + a * 136 + b * 8 + k];
                float tv2 = u2s[2 * 2176 + a * 136 + b * 8 + k];
                float tv3 = u2s[3 * 2176 + a * 136 + b * 8 + k];
                float4 fv = *(const float4*)(f2t + k * 16 + q * 4);
                float fcv[4] = { fv.x, fv.y, fv.z, fv.w };
#pragma unroll
                for (int c4 = 0; c4 < 4; c4++) {
                    acc[0][c4] += tv0 * fcv[c4]; acc[1][c4] += tv1 * fcv[c4];
                    acc[2][c4] += tv2 * fcv[c4]; acc[3][c4] += tv3 * fcv[c4];
                }
            }
            float4 bv = *(const float4*)&bias[ab * 16 + q * 4];
#pragma unroll
            for (int s = 0; s < 4; s++) {
                float4 o = make_float4(acc[s][0] + bv.x, acc[s][1] + bv.y,
                                       acc[s][2] + bv.z, acc[s][3] + bv.w);
                *(float4*)&y[(s0 + s) * 4096 + ab * 16 + q * 4] = o;
            }
        }
    }
}

// ---------------- launch ----------------
extern "C" void kernel_launch(void* const* d_in, const int* in_sizes, int n_in,
                              void* d_out, int out_size) {
    const float* x    = (const float*)d_in[0];
    const float* core = (const float*)d_in[1];
    const float* f0   = (const float*)d_in[2];
    const float* f1   = (const float*)d_in[3];
    const float* f2   = (const float*)d_in[4];
    const float* f3   = (const float*)d_in[5];
    const float* f4   = (const float*)d_in[6];
    const float* f5   = (const float*)d_in[7];
    const float* bias = (const float*)d_in[8];
    float* y = (float*)d_out;

    int N = in_sizes[0] / 4096;

    const int SMEM_C = (4 * 1152 + 4 * 2176 + 384) * 4;   // 54784

    cudaFuncSetAttribute(k_stageA, cudaFuncAttributeMaxDynamicSharedMemorySize, SMEM_A);
    cudaFuncSetAttribute(k_gemm_mma, cudaFuncAttributeMaxDynamicSharedMemorySize, GEMM_SMEM);
    cudaFuncSetAttribute(k_stageC, cudaFuncAttributeMaxDynamicSharedMemorySize, SMEM_C);

    k_stageA<<<N / 2, 128, SMEM_A>>>(x, f3, f4, f5, core);
    k_gemm_mma<<<dim3(N / 128, 4), 512, GEMM_SMEM>>>();
    k_stageC<<<N / 4, 256, SMEM_C>>>(f0, f1, f2, bias, y);
}